// round 10
// baseline (speedup 1.0000x reference)
#include <cuda_runtime.h>
#include <math.h>

// ---------------------------------------------------------------------------
// MultiHeadAttention: B=4, S=2048, D_MODEL=1024, HEADS=16, D_K=D_V=64
// Inputs (metadata order): q, k, v, mask, Wq, Wk, Wv, Wo, ln_gamma, ln_beta
// Output: concat( out[B,S,1024], attn[B,H,S,S] ) as float32
// ---------------------------------------------------------------------------

#define B_   4
#define S_   2048
#define DM   1024
#define H_   16
#define DK   64
#define BS_  (B_ * S_)                 // 8192
#define ATTN_OFF ((size_t)BS_ * DM)    // 8388608
#define NEG_INF_F (-1000000000.0f)

// Scratch (static device globals; no runtime allocation)
__device__ float g_qn [BS_ * DM];
__device__ float g_Qh [BS_ * DM];
__device__ float g_Kh [BS_ * DM];
__device__ float g_Vh [BS_ * DM];
__device__ float g_ctx[BS_ * DM];
__device__ float g_rowmax[B_ * H_ * S_];

// ---------------------------------------------------------------------------
// Block-wide sum over 256 threads (8 warps). Caller supplies 8-float smem.
// ---------------------------------------------------------------------------
__device__ __forceinline__ float blk_sum256(float v, float* sbuf) {
    #pragma unroll
    for (int o = 16; o; o >>= 1) v += __shfl_xor_sync(0xffffffffu, v, o);
    int t = threadIdx.x;
    if ((t & 31) == 0) sbuf[t >> 5] = v;
    __syncthreads();
    float r = sbuf[0] + sbuf[1] + sbuf[2] + sbuf[3] +
              sbuf[4] + sbuf[5] + sbuf[6] + sbuf[7];
    __syncthreads();
    return r;
}

// ---------------------------------------------------------------------------
// LayerNorm over rows of 1024. One block (256 thr) per row, float4 per thread.
// ---------------------------------------------------------------------------
__global__ void __launch_bounds__(256) ln_kernel(
    const float* __restrict__ x, const float* __restrict__ gamma,
    const float* __restrict__ beta, float* __restrict__ y)
{
    __shared__ float sbuf[8];
    int row = blockIdx.x;
    int t = threadIdx.x;
    const float4* xr = (const float4*)(x + (size_t)row * DM);
    float4 v = xr[t];
    float s = v.x + v.y + v.z + v.w;
    float tot = blk_sum256(s, sbuf);
    float mean = tot * (1.0f / DM);
    float dx = v.x - mean, dy = v.y - mean, dz = v.z - mean, dw = v.w - mean;
    float s2 = dx*dx + dy*dy + dz*dz + dw*dw;
    float tot2 = blk_sum256(s2, sbuf);
    float rstd = rsqrtf(tot2 * (1.0f / DM) + 1e-6f);
    float4 g  = ((const float4*)gamma)[t];
    float4 bb = ((const float4*)beta)[t];
    float4 o;
    o.x = dx * rstd * g.x + bb.x;
    o.y = dy * rstd * g.y + bb.y;
    o.z = dz * rstd * g.z + bb.z;
    o.w = dw * rstd * g.w + bb.w;
    ((float4*)(y + (size_t)row * DM))[t] = o;
}

// ---------------------------------------------------------------------------
// SGEMM: C(MxN) = A(MxK) @ B(KxN) [+ R], row-major, M%128==N%128==0, K%8==0.
// 128x128 block tile, BK=8, 256 threads, 8x8 micro-tile (split quadrants).
// ---------------------------------------------------------------------------
__global__ void __launch_bounds__(256) sgemm_kernel(
    const float* __restrict__ A, const float* __restrict__ Bm,
    const float* __restrict__ R, float* __restrict__ C,
    int M, int N, int K)
{
    __shared__ float As[8][132];
    __shared__ float Bs[8][128];
    int tid = threadIdx.x;
    int tx = tid & 15, ty = tid >> 4;
    int bm = blockIdx.y << 7, bn = blockIdx.x << 7;

    float acc[8][8];
    #pragma unroll
    for (int i = 0; i < 8; i++)
        #pragma unroll
        for (int j = 0; j < 8; j++) acc[i][j] = 0.0f;

    int arow = tid >> 1;
    int acol = (tid & 1) << 2;
    int brow = tid >> 5;
    int bcol = (tid & 31) << 2;
    const float* Ap = A + (size_t)(bm + arow) * K + acol;
    const float* Bp = Bm + (size_t)brow * N + bn + bcol;

    for (int k0 = 0; k0 < K; k0 += 8) {
        float4 av = *(const float4*)(Ap + k0);
        float4 bv = *(const float4*)(Bp + (size_t)k0 * N);
        As[acol + 0][arow] = av.x;
        As[acol + 1][arow] = av.y;
        As[acol + 2][arow] = av.z;
        As[acol + 3][arow] = av.w;
        *(float4*)&Bs[brow][bcol] = bv;
        __syncthreads();
        #pragma unroll
        for (int kk = 0; kk < 8; kk++) {
            float a[8], b[8];
            *(float4*)(a)     = *(const float4*)&As[kk][ty << 2];
            *(float4*)(a + 4) = *(const float4*)&As[kk][64 + (ty << 2)];
            *(float4*)(b)     = *(const float4*)&Bs[kk][tx << 2];
            *(float4*)(b + 4) = *(const float4*)&Bs[kk][64 + (tx << 2)];
            #pragma unroll
            for (int i = 0; i < 8; i++)
                #pragma unroll
                for (int j = 0; j < 8; j++) acc[i][j] += a[i] * b[j];
        }
        __syncthreads();
    }

    #pragma unroll
    for (int i = 0; i < 8; i++) {
        int r = bm + ((i < 4) ? ((ty << 2) + i) : (64 + (ty << 2) + i - 4));
        float* crow = C + (size_t)r * N + bn;
        float4 c0 = make_float4(acc[i][0], acc[i][1], acc[i][2], acc[i][3]);
        float4 c1 = make_float4(acc[i][4], acc[i][5], acc[i][6], acc[i][7]);
        if (R) {
            const float* rrow = R + (size_t)r * N + bn;
            float4 r0 = *(const float4*)(rrow + (tx << 2));
            float4 r1 = *(const float4*)(rrow + 64 + (tx << 2));
            c0.x += r0.x; c0.y += r0.y; c0.z += r0.z; c0.w += r0.w;
            c1.x += r1.x; c1.y += r1.y; c1.z += r1.z; c1.w += r1.w;
        }
        *(float4*)(crow + (tx << 2))      = c0;
        *(float4*)(crow + 64 + (tx << 2)) = c1;
    }
}

// ---------------------------------------------------------------------------
// Scores: attn_raw[b,h,q,k] = (Q[b,q,h,:] . K[b,k,h,:]) / 8, masked to -1e9.
// Also records per-row max. 128q x 128k tile per block, inner dim 64.
// Dynamic smem: Qs[64][132] + Ks[64][132] = 67584 B.
// ---------------------------------------------------------------------------
__global__ void __launch_bounds__(256) scores_kernel(
    const float* __restrict__ Qh, const float* __restrict__ Kh,
    const int* __restrict__ mask, float* __restrict__ attn,
    float* __restrict__ rowmax)
{
    extern __shared__ float sm[];
    float* Qs = sm;             // [64][132]  (d-major, q cols)
    float* Ks = sm + 64 * 132;  // [64][132]
    __shared__ int msk[128];

    int bh = blockIdx.y;
    int b = bh >> 4, h = bh & 15;
    int q0 = blockIdx.x << 7;
    int tid = threadIdx.x, tx = tid & 15, ty = tid >> 4;

    // Load Q tile (128 x 64), transposed + pre-scaled by 1/sqrt(64)
    {
        int q  = tid >> 1;
        int d0 = (tid & 1) << 5;
        const float* src = Qh + (size_t)(b * S_ + q0 + q) * DM + h * DK + d0;
        #pragma unroll
        for (int i = 0; i < 8; i++) {
            float4 v = *(const float4*)(src + (i << 2));
            int d = d0 + (i << 2);
            Qs[(d + 0) * 132 + q] = v.x * 0.125f;
            Qs[(d + 1) * 132 + q] = v.y * 0.125f;
            Qs[(d + 2) * 132 + q] = v.z * 0.125f;
            Qs[(d + 3) * 132 + q] = v.w * 0.125f;
        }
    }

    float rmax[8];
    #pragma unroll
    for (int i = 0; i < 8; i++) rmax[i] = -3.0e38f;

    for (int kt = 0; kt < 16; kt++) {
        int kb = kt << 7;
        __syncthreads();
        {
            int kq = tid >> 1;
            int d0 = (tid & 1) << 5;
            const float* src = Kh + (size_t)(b * S_ + kb + kq) * DM + h * DK + d0;
            #pragma unroll
            for (int i = 0; i < 8; i++) {
                float4 v = *(const float4*)(src + (i << 2));
                int d = d0 + (i << 2);
                Ks[(d + 0) * 132 + kq] = v.x;
                Ks[(d + 1) * 132 + kq] = v.y;
                Ks[(d + 2) * 132 + kq] = v.z;
                Ks[(d + 3) * 132 + kq] = v.w;
            }
            if (tid < 128) msk[tid] = mask[b * S_ + kb + tid];
        }
        __syncthreads();

        float acc[8][8];
        #pragma unroll
        for (int i = 0; i < 8; i++)
            #pragma unroll
            for (int j = 0; j < 8; j++) acc[i][j] = 0.0f;

        #pragma unroll 16
        for (int kk = 0; kk < 64; kk++) {
            float a[8], bb[8];
            *(float4*)(a)      = *(const float4*)&Qs[kk * 132 + (ty << 2)];
            *(float4*)(a + 4)  = *(const float4*)&Qs[kk * 132 + 64 + (ty << 2)];
            *(float4*)(bb)     = *(const float4*)&Ks[kk * 132 + (tx << 2)];
            *(float4*)(bb + 4) = *(const float4*)&Ks[kk * 132 + 64 + (tx << 2)];
            #pragma unroll
            for (int i = 0; i < 8; i++)
                #pragma unroll
                for (int j = 0; j < 8; j++) acc[i][j] += a[i] * bb[j];
        }

        #pragma unroll
        for (int i = 0; i < 8; i++) {
            int qr = (i < 4) ? ((ty << 2) + i) : (64 + (ty << 2) + i - 4);
            float* orow = attn + ((size_t)bh * S_ + q0 + qr) * S_ + kb;
            float o0[4], o1[4];
            #pragma unroll
            for (int j = 0; j < 4; j++) {
                float s = msk[(tx << 2) + j] ? acc[i][j] : NEG_INF_F;
                rmax[i] = fmaxf(rmax[i], s);
                o0[j] = s;
            }
            #pragma unroll
            for (int j = 0; j < 4; j++) {
                float s = msk[64 + (tx << 2) + j] ? acc[i][4 + j] : NEG_INF_F;
                rmax[i] = fmaxf(rmax[i], s);
                o1[j] = s;
            }
            *(float4*)(orow + (tx << 2))      = make_float4(o0[0], o0[1], o0[2], o0[3]);
            *(float4*)(orow + 64 + (tx << 2)) = make_float4(o1[0], o1[1], o1[2], o1[3]);
        }
    }

    // Reduce row max across the 16 tx lanes (width-16 shuffle groups)
    #pragma unroll
    for (int i = 0; i < 8; i++) {
        float m = rmax[i];
        m = fmaxf(m, __shfl_xor_sync(0xffffffffu, m, 1, 16));
        m = fmaxf(m, __shfl_xor_sync(0xffffffffu, m, 2, 16));
        m = fmaxf(m, __shfl_xor_sync(0xffffffffu, m, 4, 16));
        m = fmaxf(m, __shfl_xor_sync(0xffffffffu, m, 8, 16));
        if (tx == 0) {
            int qr = (i < 4) ? ((ty << 2) + i) : (64 + (ty << 2) + i - 4);
            rowmax[(size_t)bh * S_ + q0 + qr] = m;
        }
    }
}

// ---------------------------------------------------------------------------
// Row softmax over 2048-wide rows, in place. One block per row.
// ---------------------------------------------------------------------------
__global__ void __launch_bounds__(256) softmax_kernel(
    float* __restrict__ attn, const float* __restrict__ rowmax)
{
    __shared__ float sbuf[8];
    size_t row = blockIdx.x;
    float* p = attn + row * S_;
    float m = rowmax[row];
    int t = threadIdx.x;
    float4 v0 = ((const float4*)p)[t];
    float4 v1 = ((const float4*)p)[t + 256];
    float e[8];
    e[0] = __expf(v0.x - m); e[1] = __expf(v0.y - m);
    e[2] = __expf(v0.z - m); e[3] = __expf(v0.w - m);
    e[4] = __expf(v1.x - m); e[5] = __expf(v1.y - m);
    e[6] = __expf(v1.z - m); e[7] = __expf(v1.w - m);
    float s = e[0] + e[1] + e[2] + e[3] + e[4] + e[5] + e[6] + e[7];
    float l = blk_sum256(s, sbuf);
    float inv = 1.0f / l;
    ((float4*)p)[t]       = make_float4(e[0]*inv, e[1]*inv, e[2]*inv, e[3]*inv);
    ((float4*)p)[t + 256] = make_float4(e[4]*inv, e[5]*inv, e[6]*inv, e[7]*inv);
}

// ---------------------------------------------------------------------------
// PV: ctx[b,q,h,:] = attn[b,h,q,:] @ V[b,:,h,:].  Per (b,h): (2048x2048)@(2048x64).
// 128x64 block tile, BK=16, 256 threads, 8x4 micro-tile.
// ---------------------------------------------------------------------------
__global__ void __launch_bounds__(256) pv_kernel(
    const float* __restrict__ attn, const float* __restrict__ Vh,
    float* __restrict__ ctx)
{
    __shared__ float Ps[16][132];
    __shared__ float Vs[16][68];
    int bh = blockIdx.y;
    int b = bh >> 4, h = bh & 15;
    int m0 = blockIdx.x << 7;
    int tid = threadIdx.x, tx = tid & 15, ty = tid >> 4;

    float acc[8][4];
    #pragma unroll
    for (int i = 0; i < 8; i++)
        #pragma unroll
        for (int j = 0; j < 4; j++) acc[i][j] = 0.0f;

    const float* P = attn + ((size_t)bh * S_ + m0) * S_;
    const float* V = Vh + (size_t)b * S_ * DM + h * DK;
    int prow = tid >> 1;
    int pk0  = (tid & 1) << 3;
    int vk   = tid >> 4;
    int vn   = (tid & 15) << 2;

    for (int k0 = 0; k0 < S_; k0 += 16) {
        __syncthreads();
        float4 p0 = *(const float4*)(P + (size_t)prow * S_ + k0 + pk0);
        float4 p1 = *(const float4*)(P + (size_t)prow * S_ + k0 + pk0 + 4);
        Ps[pk0 + 0][prow] = p0.x; Ps[pk0 + 1][prow] = p0.y;
        Ps[pk0 + 2][prow] = p0.z; Ps[pk0 + 3][prow] = p0.w;
        Ps[pk0 + 4][prow] = p1.x; Ps[pk0 + 5][prow] = p1.y;
        Ps[pk0 + 6][prow] = p1.z; Ps[pk0 + 7][prow] = p1.w;
        *(float4*)&Vs[vk][vn] = *(const float4*)(V + (size_t)(k0 + vk) * DM + vn);
        __syncthreads();
        #pragma unroll
        for (int kk = 0; kk < 16; kk++) {
            float a[8], bb[4];
            *(float4*)(a)     = *(const float4*)&Ps[kk][ty << 2];
            *(float4*)(a + 4) = *(const float4*)&Ps[kk][64 + (ty << 2)];
            *(float4*)(bb)    = *(const float4*)&Vs[kk][tx << 2];
            #pragma unroll
            for (int i = 0; i < 8; i++)
                #pragma unroll
                for (int j = 0; j < 4; j++) acc[i][j] += a[i] * bb[j];
        }
    }

    #pragma unroll
    for (int i = 0; i < 8; i++) {
        int r = (i < 4) ? ((ty << 2) + i) : (64 + (ty << 2) + i - 4);
        float4 c = make_float4(acc[i][0], acc[i][1], acc[i][2], acc[i][3]);
        *(float4*)(ctx + (size_t)(b * S_ + m0 + r) * DM + h * DK + (tx << 2)) = c;
    }
}

// ---------------------------------------------------------------------------
extern "C" void kernel_launch(void* const* d_in, const int* in_sizes, int n_in,
                              void* d_out, int out_size)
{
    const float* q    = (const float*)d_in[0];
    const float* k    = (const float*)d_in[1];
    const float* v    = (const float*)d_in[2];
    const int*   mask = (const int*)  d_in[3];
    const float* Wq   = (const float*)d_in[4];
    const float* Wk   = (const float*)d_in[5];
    const float* Wv   = (const float*)d_in[6];
    const float* Wo   = (const float*)d_in[7];
    const float* lg   = (const float*)d_in[8];
    const float* lb   = (const float*)d_in[9];

    float* out  = (float*)d_out;
    float* attn = out + ATTN_OFF;

    float *qn, *Qh, *Kh, *Vh, *ctx, *rmx;
    cudaGetSymbolAddress((void**)&qn,  g_qn);
    cudaGetSymbolAddress((void**)&Qh,  g_Qh);
    cudaGetSymbolAddress((void**)&Kh,  g_Kh);
    cudaGetSymbolAddress((void**)&Vh,  g_Vh);
    cudaGetSymbolAddress((void**)&ctx, g_ctx);
    cudaGetSymbolAddress((void**)&rmx, g_rowmax);

    cudaFuncSetAttribute(scores_kernel,
                         cudaFuncAttributeMaxDynamicSharedMemorySize, 67584);

    // 1. LayerNorm(q)
    ln_kernel<<<BS_, 256>>>(q, lg, lb, qn);

    // 2-4. Projections
    dim3 g8(DM / 128, BS_ / 128);   // (8, 64)
    sgemm_kernel<<<g8, 256>>>(qn, Wq, nullptr, Qh, BS_, DM, DM);
    sgemm_kernel<<<g8, 256>>>(k,  Wk, nullptr, Kh, BS_, DM, DM);
    sgemm_kernel<<<g8, 256>>>(v,  Wv, nullptr, Vh, BS_, DM, DM);

    // 5. Raw masked scores + row max
    scores_kernel<<<dim3(S_ / 128, B_ * H_), 256, 67584>>>(Qh, Kh, mask, attn, rmx);

    // 6. Softmax in place
    softmax_kernel<<<B_ * H_ * S_, 256>>>(attn, rmx);

    // 7. PV
    pv_kernel<<<dim3(S_ / 128, B_ * H_), 256>>>(attn, Vh, ctx);

    // 8. Output projection + residual
    sgemm_kernel<<<g8, 256>>>(ctx, Wo, q, out, BS_, DM, DM);
}

// round 12
// speedup vs baseline: 1.3531x; 1.3531x over previous
#include <cuda_runtime.h>
#include <cuda_bf16.h>
#include <math.h>
#include <stdint.h>

// ---------------------------------------------------------------------------
// MultiHeadAttention: B=4, S=2048, D_MODEL=1024, HEADS=16, D_K=D_V=64
// Output: concat( out[B,S,1024], attn[B,H,S,S] ) as float32
// Projections: mma.sync bf16 hi/lo split-3 (baseline PTX -> HMMA on sm_103a).
// ---------------------------------------------------------------------------

#define B_   4
#define S_   2048
#define DM   1024
#define H_   16
#define DK   64
#define BS_  (B_ * S_)                 // 8192
#define ATTN_OFF ((size_t)BS_ * DM)
#define NEG_INF_F (-1000000000.0f)

// Scratch (static device globals; no runtime allocation)
__device__ float g_qn [BS_ * DM];
__device__ float g_Qh [BS_ * DM];
__device__ float g_Kh [BS_ * DM];
__device__ float g_Vh [BS_ * DM];
__device__ float g_ctx[BS_ * DM];
__device__ float g_rowmax[B_ * H_ * S_];
// Pre-transposed, hi/lo-split weights: [N=1024][K=1024] bf16
__device__ __align__(16) __nv_bfloat16 g_WTh[4][DM * DM];
__device__ __align__(16) __nv_bfloat16 g_WTl[4][DM * DM];
// Activation hi/lo split buffers (reused for each GEMM, stream-ordered)
__device__ __align__(16) __nv_bfloat16 g_Ah[BS_ * DM];
__device__ __align__(16) __nv_bfloat16 g_Al[BS_ * DM];

// ============================ PTX helpers ==================================
__device__ __forceinline__ uint32_t smem_u32(const void* p) {
    uint32_t a;
    asm("{ .reg .u64 t; cvta.to.shared.u64 t, %1; cvt.u32.u64 %0, t; }"
        : "=r"(a) : "l"(p));
    return a;
}
__device__ __forceinline__ void ldmat4(uint32_t* r, uint32_t addr) {
    asm volatile("ldmatrix.sync.aligned.m8n8.x4.shared.b16 {%0,%1,%2,%3}, [%4];"
                 : "=r"(r[0]), "=r"(r[1]), "=r"(r[2]), "=r"(r[3]) : "r"(addr));
}
__device__ __forceinline__ void ldmat2(uint32_t* r, uint32_t addr) {
    asm volatile("ldmatrix.sync.aligned.m8n8.x2.shared.b16 {%0,%1}, [%2];"
                 : "=r"(r[0]), "=r"(r[1]) : "r"(addr));
}
__device__ __forceinline__ void mma_bf16(float* d, const uint32_t* a,
                                         const uint32_t* b) {
    asm volatile(
        "mma.sync.aligned.m16n8k16.row.col.f32.bf16.bf16.f32 "
        "{%0,%1,%2,%3}, {%4,%5,%6,%7}, {%8,%9}, {%0,%1,%2,%3};"
        : "+f"(d[0]), "+f"(d[1]), "+f"(d[2]), "+f"(d[3])
        : "r"(a[0]), "r"(a[1]), "r"(a[2]), "r"(a[3]), "r"(b[0]), "r"(b[1]));
}
__device__ __forceinline__ void cpasync16(uint32_t dst, const void* src) {
    asm volatile("cp.async.cg.shared.global [%0], [%1], 16;"
                 :: "r"(dst), "l"(src));
}
#define CP_COMMIT() asm volatile("cp.async.commit_group;" ::: "memory")
#define CP_WAIT1()  asm volatile("cp.async.wait_group 1;"  ::: "memory")
#define CP_WAIT0()  asm volatile("cp.async.wait_group 0;"  ::: "memory")

// ---------------------------------------------------------------------------
// Weight transpose + bf16 hi/lo split:  W[K][N] fp32 -> Th/Tl[N][K] bf16
// ---------------------------------------------------------------------------
__global__ void __launch_bounds__(256) wtrans_kernel(
    const float* __restrict__ W, __nv_bfloat16* __restrict__ Th,
    __nv_bfloat16* __restrict__ Tl)
{
    __shared__ float t[32][33];
    int bx = blockIdx.x << 5;   // n
    int by = blockIdx.y << 5;   // k
    int x = threadIdx.x & 31, y = threadIdx.x >> 5;
    #pragma unroll
    for (int r = 0; r < 32; r += 8)
        t[y + r][x] = W[(size_t)(by + y + r) * DM + bx + x];
    __syncthreads();
    #pragma unroll
    for (int r = 0; r < 32; r += 8) {
        int nl = y + r;
        float v = t[x][nl];
        __nv_bfloat16 h = __float2bfloat16(v);
        __nv_bfloat16 l = __float2bfloat16(v - __bfloat162float(h));
        size_t o = (size_t)(bx + nl) * DM + by + x;
        Th[o] = h;
        Tl[o] = l;
    }
}

// ---------------------------------------------------------------------------
// Activation split: fp32 -> bf16 hi + bf16 lo (elementwise, float4 vectorized)
// ---------------------------------------------------------------------------
union BPack { __nv_bfloat16 b[4]; uint2 u; };

__global__ void __launch_bounds__(256) asplit_kernel(
    const float4* __restrict__ A, uint2* __restrict__ Ah,
    uint2* __restrict__ Al)
{
    int i = blockIdx.x * 256 + threadIdx.x;
    float4 v = A[i];
    float f[4] = {v.x, v.y, v.z, v.w};
    BPack ph, pl;
    #pragma unroll
    for (int j = 0; j < 4; j++) {
        __nv_bfloat16 h = __float2bfloat16(f[j]);
        ph.b[j] = h;
        pl.b[j] = __float2bfloat16(f[j] - __bfloat162float(h));
    }
    Ah[i] = ph.u;
    Al[i] = pl.u;
}

// ---------------------------------------------------------------------------
// HMMA GEMM: C[8192][1024] = (Ah+Al)[8192][1024] @ (Bh+Bl)^T  (+R)
// B stored [n][k] (col-major k x n). 128x128 block tile, KC=32 chunks,
// double-buffered cp.async. 8 warps, warp tile 64x32, m16n8k16 bf16 split-3.
// Stage layout (elems): Ah[128*40] | Al | Bh | Bl  (row pad 40 elems = 80B)
// ---------------------------------------------------------------------------
#define STG_      40
#define ARR_B     (128 * STG_ * 2)        // 10240 bytes per array
#define STAGE_B   (4 * ARR_B)             // 40960 bytes per stage
#define GEMM_SMEM (2 * STAGE_B)           // 81920

__global__ void __launch_bounds__(256, 2) hmma_gemm(
    const __nv_bfloat16* __restrict__ Ah, const __nv_bfloat16* __restrict__ Al,
    const __nv_bfloat16* __restrict__ Bh, const __nv_bfloat16* __restrict__ Bl,
    const float* __restrict__ R, float* __restrict__ C)
{
    extern __shared__ char dynsm[];
    uint32_t sbase = smem_u32(dynsm);

    int tid = threadIdx.x, lane = tid & 31, wid = tid >> 5;
    int wm = (wid & 1) << 6;       // 0 / 64
    int wn = (wid >> 1) << 5;      // 0 / 32 / 64 / 96
    int bm = blockIdx.y << 7, bn = blockIdx.x << 7;

    float acc[4][4][4];
    #pragma unroll
    for (int mt = 0; mt < 4; mt++)
        #pragma unroll
        for (int nt = 0; nt < 4; nt++)
            #pragma unroll
            for (int e = 0; e < 4; e++) acc[mt][nt][e] = 0.0f;

    // Loader indices: 512 16B-segments per array, 2 per thread
    int l_row0 = (tid << 1) >> 2;          // idx = tid*2
    int l_seg0 = (tid << 1) & 3;
    int l_row1 = ((tid << 1) | 1) >> 2;
    int l_seg1 = ((tid << 1) | 1) & 3;

    #define LOAD_STAGE(s, kc) do {                                            \
        uint32_t sb_ = sbase + (s) * STAGE_B;                                 \
        int k0_ = (kc) << 5;                                                  \
        uint32_t d0_ = sb_ + l_row0 * 80 + l_seg0 * 16;                       \
        uint32_t d1_ = sb_ + l_row1 * 80 + l_seg1 * 16;                       \
        const __nv_bfloat16* a0_ = Ah + (size_t)(bm + l_row0) * DM + k0_ + l_seg0 * 8; \
        const __nv_bfloat16* a1_ = Ah + (size_t)(bm + l_row1) * DM + k0_ + l_seg1 * 8; \
        const __nv_bfloat16* b0_ = Bh + (size_t)(bn + l_row0) * DM + k0_ + l_seg0 * 8; \
        const __nv_bfloat16* b1_ = Bh + (size_t)(bn + l_row1) * DM + k0_ + l_seg1 * 8; \
        cpasync16(d0_,              a0_);                                     \
        cpasync16(d0_ + ARR_B,      a0_ + (Al - Ah));                         \
        cpasync16(d0_ + 2 * ARR_B,  b0_);                                     \
        cpasync16(d0_ + 3 * ARR_B,  b0_ + (Bl - Bh));                         \
        cpasync16(d1_,              a1_);                                     \
        cpasync16(d1_ + ARR_B,      a1_ + (Al - Ah));                         \
        cpasync16(d1_ + 2 * ARR_B,  b1_);                                     \
        cpasync16(d1_ + 3 * ARR_B,  b1_ + (Bl - Bh));                         \
        CP_COMMIT();                                                          \
    } while (0)

    LOAD_STAGE(0, 0);

    const int NK = DM / 32;   // 32 chunks
    for (int kc = 0; kc < NK; kc++) {
        int s = kc & 1;
        if (kc + 1 < NK) {
            LOAD_STAGE(s ^ 1, kc + 1);
            CP_WAIT1();
        } else {
            CP_WAIT0();
        }
        __syncthreads();

        uint32_t sb = sbase + s * STAGE_B;
        #pragma unroll
        for (int ks = 0; ks < 2; ks++) {
            int kb = ks << 4;
            // A fragments (hi and lo), 4 m-tiles
            uint32_t ah[4][4], al[4][4];
            uint32_t a_addr = sb +
                (((wm + (lane & 15)) * STG_ + kb + ((lane >> 4) << 3)) << 1);
            #pragma unroll
            for (int mt = 0; mt < 4; mt++) {
                ldmat4(ah[mt], a_addr + mt * (16 * STG_ * 2));
                ldmat4(al[mt], a_addr + mt * (16 * STG_ * 2) + ARR_B);
            }
            // B fragments per n-tile, then MMAs
            uint32_t b_addr = sb + 2 * ARR_B +
                (((wn + (lane & 7)) * STG_ + kb + (((lane >> 3) & 1) << 3)) << 1);
            #pragma unroll
            for (int nt = 0; nt < 4; nt++) {
                uint32_t bh[2], bl[2];
                ldmat2(bh, b_addr + nt * (8 * STG_ * 2));
                ldmat2(bl, b_addr + nt * (8 * STG_ * 2) + ARR_B);
                #pragma unroll
                for (int mt = 0; mt < 4; mt++) {
                    mma_bf16(acc[mt][nt], ah[mt], bh);
                    mma_bf16(acc[mt][nt], ah[mt], bl);
                    mma_bf16(acc[mt][nt], al[mt], bh);
                }
            }
        }
        __syncthreads();
    }

    // Epilogue: each mma tile -> two float2 stores per lane
    int rq = lane >> 2, cq = (lane & 3) << 1;
    #pragma unroll
    for (int mt = 0; mt < 4; mt++) {
        int r0 = bm + wm + (mt << 4) + rq;
        #pragma unroll
        for (int nt = 0; nt < 4; nt++) {
            int c = bn + wn + (nt << 3) + cq;
            float2 v0 = make_float2(acc[mt][nt][0], acc[mt][nt][1]);
            float2 v1 = make_float2(acc[mt][nt][2], acc[mt][nt][3]);
            if (R) {
                float2 r0v = *(const float2*)(R + (size_t)r0 * DM + c);
                float2 r1v = *(const float2*)(R + (size_t)(r0 + 8) * DM + c);
                v0.x += r0v.x; v0.y += r0v.y;
                v1.x += r1v.x; v1.y += r1v.y;
            }
            *(float2*)(C + (size_t)r0 * DM + c) = v0;
            *(float2*)(C + (size_t)(r0 + 8) * DM + c) = v1;
        }
    }
    #undef LOAD_STAGE
}

// ---------------------------------------------------------------------------
// Block-wide sum over 256 threads (8 warps).
// ---------------------------------------------------------------------------
__device__ __forceinline__ float blk_sum256(float v, float* sbuf) {
    #pragma unroll
    for (int o = 16; o; o >>= 1) v += __shfl_xor_sync(0xffffffffu, v, o);
    int t = threadIdx.x;
    if ((t & 31) == 0) sbuf[t >> 5] = v;
    __syncthreads();
    float r = sbuf[0] + sbuf[1] + sbuf[2] + sbuf[3] +
              sbuf[4] + sbuf[5] + sbuf[6] + sbuf[7];
    __syncthreads();
    return r;
}

// ---------------------------------------------------------------------------
// LayerNorm over rows of 1024.
// ---------------------------------------------------------------------------
__global__ void __launch_bounds__(256) ln_kernel(
    const float* __restrict__ x, const float* __restrict__ gamma,
    const float* __restrict__ beta, float* __restrict__ y)
{
    __shared__ float sbuf[8];
    int rowi = blockIdx.x;
    int t = threadIdx.x;
    const float4* xr = (const float4*)(x + (size_t)rowi * DM);
    float4 v = xr[t];
    float s = v.x + v.y + v.z + v.w;
    float tot = blk_sum256(s, sbuf);
    float mean = tot * (1.0f / DM);
    float dx = v.x - mean, dy = v.y - mean, dz = v.z - mean, dw = v.w - mean;
    float s2 = dx*dx + dy*dy + dz*dz + dw*dw;
    float tot2 = blk_sum256(s2, sbuf);
    float rstd = rsqrtf(tot2 * (1.0f / DM) + 1e-6f);
    float4 g  = ((const float4*)gamma)[t];
    float4 bb = ((const float4*)beta)[t];
    float4 o;
    o.x = dx * rstd * g.x + bb.x;
    o.y = dy * rstd * g.y + bb.y;
    o.z = dz * rstd * g.z + bb.z;
    o.w = dw * rstd * g.w + bb.w;
    ((float4*)(y + (size_t)rowi * DM))[t] = o;
}

// ---------------------------------------------------------------------------
// Scores (fp32 SIMT): 128q x 128k tiles, full k-loop per block.
// ---------------------------------------------------------------------------
__global__ void __launch_bounds__(256) scores_kernel(
    const float* __restrict__ Qh, const float* __restrict__ Kh,
    const int* __restrict__ mask, float* __restrict__ attn,
    float* __restrict__ rowmax)
{
    extern __shared__ float sm[];
    float* Qs = sm;
    float* Ks = sm + 64 * 132;
    __shared__ int msk[128];

    int bh = blockIdx.y;
    int b = bh >> 4, h = bh & 15;
    int q0 = blockIdx.x << 7;
    int tid = threadIdx.x, tx = tid & 15, ty = tid >> 4;

    {
        int q  = tid >> 1;
        int d0 = (tid & 1) << 5;
        const float* src = Qh + (size_t)(b * S_ + q0 + q) * DM + h * DK + d0;
        #pragma unroll
        for (int i = 0; i < 8; i++) {
            float4 v = *(const float4*)(src + (i << 2));
            int d = d0 + (i << 2);
            Qs[(d + 0) * 132 + q] = v.x * 0.125f;
            Qs[(d + 1) * 132 + q] = v.y * 0.125f;
            Qs[(d + 2) * 132 + q] = v.z * 0.125f;
            Qs[(d + 3) * 132 + q] = v.w * 0.125f;
        }
    }

    float rmax[8];
    #pragma unroll
    for (int i = 0; i < 8; i++) rmax[i] = -3.0e38f;

    for (int kt = 0; kt < 16; kt++) {
        int kb = kt << 7;
        __syncthreads();
        {
            int kq = tid >> 1;
            int d0 = (tid & 1) << 5;
            const float* src = Kh + (size_t)(b * S_ + kb + kq) * DM + h * DK + d0;
            #pragma unroll
            for (int i = 0; i < 8; i++) {
                float4 v = *(const float4*)(src + (i << 2));
                int d = d0 + (i << 2);
                Ks[(d + 0) * 132 + kq] = v.x;
                Ks[(d + 1) * 132 + kq] = v.y;
                Ks[(d + 2) * 132 + kq] = v.z;
                Ks[(d + 3) * 132 + kq] = v.w;
            }
            if (tid < 128) msk[tid] = mask[b * S_ + kb + tid];
        }
        __syncthreads();

        float acc[8][8];
        #pragma unroll
        for (int i = 0; i < 8; i++)
            #pragma unroll
            for (int j = 0; j < 8; j++) acc[i][j] = 0.0f;

        #pragma unroll 16
        for (int kk = 0; kk < 64; kk++) {
            float a[8], bb[8];
            *(float4*)(a)      = *(const float4*)&Qs[kk * 132 + (ty << 2)];
            *(float4*)(a + 4)  = *(const float4*)&Qs[kk * 132 + 64 + (ty << 2)];
            *(float4*)(bb)     = *(const float4*)&Ks[kk * 132 + (tx << 2)];
            *(float4*)(bb + 4) = *(const float4*)&Ks[kk * 132 + 64 + (tx << 2)];
            #pragma unroll
            for (int i = 0; i < 8; i++)
                #pragma unroll
                for (int j = 0; j < 8; j++) acc[i][j] += a[i] * bb[j];
        }

        #pragma unroll
        for (int i = 0; i < 8; i++) {
            int qr = (i < 4) ? ((ty << 2) + i) : (64 + (ty << 2) + i - 4);
            float* orow = attn + ((size_t)bh * S_ + q0 + qr) * S_ + kb;
            float o0[4], o1[4];
            #pragma unroll
            for (int j = 0; j < 4; j++) {
                float s = msk[(tx << 2) + j] ? acc[i][j] : NEG_INF_F;
                rmax[i] = fmaxf(rmax[i], s);
                o0[j] = s;
            }
            #pragma unroll
            for (int j = 0; j < 4; j++) {
                float s = msk[64 + (tx << 2) + j] ? acc[i][4 + j] : NEG_INF_F;
                rmax[i] = fmaxf(rmax[i], s);
                o1[j] = s;
            }
            *(float4*)(orow + (tx << 2))      = make_float4(o0[0], o0[1], o0[2], o0[3]);
            *(float4*)(orow + 64 + (tx << 2)) = make_float4(o1[0], o1[1], o1[2], o1[3]);
        }
    }

    #pragma unroll
    for (int i = 0; i < 8; i++) {
        float m = rmax[i];
        m = fmaxf(m, __shfl_xor_sync(0xffffffffu, m, 1, 16));
        m = fmaxf(m, __shfl_xor_sync(0xffffffffu, m, 2, 16));
        m = fmaxf(m, __shfl_xor_sync(0xffffffffu, m, 4, 16));
        m = fmaxf(m, __shfl_xor_sync(0xffffffffu, m, 8, 16));
        if (tx == 0) {
            int qr = (i < 4) ? ((ty << 2) + i) : (64 + (ty << 2) + i - 4);
            rowmax[(size_t)bh * S_ + q0 + qr] = m;
        }
    }
}

// ---------------------------------------------------------------------------
// Row softmax over 2048-wide rows, in place.
// ---------------------------------------------------------------------------
__global__ void __launch_bounds__(256) softmax_kernel(
    float* __restrict__ attn, const float* __restrict__ rowmax)
{
    __shared__ float sbuf[8];
    size_t rowi = blockIdx.x;
    float* p = attn + rowi * S_;
    float m = rowmax[rowi];
    int t = threadIdx.x;
    float4 v0 = ((const float4*)p)[t];
    float4 v1 = ((const float4*)p)[t + 256];
    float e[8];
    e[0] = __expf(v0.x - m); e[1] = __expf(v0.y - m);
    e[2] = __expf(v0.z - m); e[3] = __expf(v0.w - m);
    e[4] = __expf(v1.x - m); e[5] = __expf(v1.y - m);
    e[6] = __expf(v1.z - m); e[7] = __expf(v1.w - m);
    float s = e[0] + e[1] + e[2] + e[3] + e[4] + e[5] + e[6] + e[7];
    float l = blk_sum256(s, sbuf);
    float inv = 1.0f / l;
    ((float4*)p)[t]       = make_float4(e[0]*inv, e[1]*inv, e[2]*inv, e[3]*inv);
    ((float4*)p)[t + 256] = make_float4(e[4]*inv, e[5]*inv, e[6]*inv, e[7]*inv);
}

// ---------------------------------------------------------------------------
// PV (fp32 SIMT)
// ---------------------------------------------------------------------------
__global__ void __launch_bounds__(256) pv_kernel(
    const float* __restrict__ attn, const float* __restrict__ Vh,
    float* __restrict__ ctx)
{
    __shared__ float Ps[16][132];
    __shared__ float Vs[16][68];
    int bh = blockIdx.y;
    int b = bh >> 4, h = bh & 15;
    int m0 = blockIdx.x << 7;
    int tid = threadIdx.x, tx = tid & 15, ty = tid >> 4;

    float acc[8][4];
    #pragma unroll
    for (int i = 0; i < 8; i++)
        #pragma unroll
        for (int j = 0; j < 4; j++) acc[i][j] = 0.0f;

    const float* P = attn + ((size_t)bh * S_ + m0) * S_;
    const float* V = Vh + (size_t)b * S_ * DM + h * DK;
    int prow = tid >> 1;
    int pk0  = (tid & 1) << 3;
    int vk   = tid >> 4;
    int vn   = (tid & 15) << 2;

    for (int k0 = 0; k0 < S_; k0 += 16) {
        __syncthreads();
        float4 p0 = *(const float4*)(P + (size_t)prow * S_ + k0 + pk0);
        float4 p1 = *(const float4*)(P + (size_t)prow * S_ + k0 + pk0 + 4);
        Ps[pk0 + 0][prow] = p0.x; Ps[pk0 + 1][prow] = p0.y;
        Ps[pk0 + 2][prow] = p0.z; Ps[pk0 + 3][prow] = p0.w;
        Ps[pk0 + 4][prow] = p1.x; Ps[pk0 + 5][prow] = p1.y;
        Ps[pk0 + 6][prow] = p1.z; Ps[pk0 + 7][prow] = p1.w;
        *(float4*)&Vs[vk][vn] = *(const float4*)(V + (size_t)(k0 + vk) * DM + vn);
        __syncthreads();
        #pragma unroll
        for (int kk = 0; kk < 16; kk++) {
            float a[8], bb[4];
            *(float4*)(a)     = *(const float4*)&Ps[kk][ty << 2];
            *(float4*)(a + 4) = *(const float4*)&Ps[kk][64 + (ty << 2)];
            *(float4*)(bb)    = *(const float4*)&Vs[kk][tx << 2];
            #pragma unroll
            for (int i = 0; i < 8; i++)
                #pragma unroll
                for (int j = 0; j < 4; j++) acc[i][j] += a[i] * bb[j];
        }
    }

    #pragma unroll
    for (int i = 0; i < 8; i++) {
        int r = (i < 4) ? ((ty << 2) + i) : (64 + (ty << 2) + i - 4);
        float4 c = make_float4(acc[i][0], acc[i][1], acc[i][2], acc[i][3]);
        *(float4*)(ctx + (size_t)(b * S_ + m0 + r) * DM + h * DK + (tx << 2)) = c;
    }
}

// ---------------------------------------------------------------------------
extern "C" void kernel_launch(void* const* d_in, const int* in_sizes, int n_in,
                              void* d_out, int out_size)
{
    const float* q    = (const float*)d_in[0];
    const float* k    = (const float*)d_in[1];
    const float* v    = (const float*)d_in[2];
    const int*   mask = (const int*)  d_in[3];
    const float* Wq   = (const float*)d_in[4];
    const float* Wk   = (const float*)d_in[5];
    const float* Wv   = (const float*)d_in[6];
    const float* Wo   = (const float*)d_in[7];
    const float* lg   = (const float*)d_in[8];
    const float* lb   = (const float*)d_in[9];

    float* out  = (float*)d_out;
    float* attn = out + ATTN_OFF;

    float *qn, *Qh, *Kh, *Vh, *ctx, *rmx;
    __nv_bfloat16 *WTh, *WTl, *Ah, *Al;
    cudaGetSymbolAddress((void**)&qn,  g_qn);
    cudaGetSymbolAddress((void**)&Qh,  g_Qh);
    cudaGetSymbolAddress((void**)&Kh,  g_Kh);
    cudaGetSymbolAddress((void**)&Vh,  g_Vh);
    cudaGetSymbolAddress((void**)&ctx, g_ctx);
    cudaGetSymbolAddress((void**)&rmx, g_rowmax);
    cudaGetSymbolAddress((void**)&WTh, g_WTh);
    cudaGetSymbolAddress((void**)&WTl, g_WTl);
    cudaGetSymbolAddress((void**)&Ah,  g_Ah);
    cudaGetSymbolAddress((void**)&Al,  g_Al);

    cudaFuncSetAttribute(scores_kernel,
                         cudaFuncAttributeMaxDynamicSharedMemorySize, 67584);
    cudaFuncSetAttribute(hmma_gemm,
                         cudaFuncAttributeMaxDynamicSharedMemorySize, GEMM_SMEM);

    const int WSZ = DM * DM;
    dim3 gt(32, 32);

    // 0. Pre-transpose + split weights into bf16 hi/lo [N][K]
    wtrans_kernel<<<gt, 256>>>(Wq, WTh + 0 * WSZ, WTl + 0 * WSZ);
    wtrans_kernel<<<gt, 256>>>(Wk, WTh + 1 * WSZ, WTl + 1 * WSZ);
    wtrans_kernel<<<gt, 256>>>(Wv, WTh + 2 * WSZ, WTl + 2 * WSZ);
    wtrans_kernel<<<gt, 256>>>(Wo, WTh + 3 * WSZ, WTl + 3 * WSZ);

    // 1. LayerNorm(q)
    ln_kernel<<<BS_, 256>>>(q, lg, lb, qn);

    const int ASPLIT_G = BS_ * DM / 4 / 256;   // 8192 blocks
    dim3 gg(DM / 128, BS_ / 128);              // (8, 64)

    // 2-4. Projections on HMMA tensor cores
    asplit_kernel<<<ASPLIT_G, 256>>>((const float4*)qn, (uint2*)Ah, (uint2*)Al);
    hmma_gemm<<<gg, 256, GEMM_SMEM>>>(Ah, Al, WTh + 0 * WSZ, WTl + 0 * WSZ, nullptr, Qh);
    asplit_kernel<<<ASPLIT_G, 256>>>((const float4*)k, (uint2*)Ah, (uint2*)Al);
    hmma_gemm<<<gg, 256, GEMM_SMEM>>>(Ah, Al, WTh + 1 * WSZ, WTl + 1 * WSZ, nullptr, Kh);
    asplit_kernel<<<ASPLIT_G, 256>>>((const float4*)v, (uint2*)Ah, (uint2*)Al);
    hmma_gemm<<<gg, 256, GEMM_SMEM>>>(Ah, Al, WTh + 2 * WSZ, WTl + 2 * WSZ, nullptr, Vh);

    // 5. Raw masked scores + row max
    scores_kernel<<<dim3(S_ / 128, B_ * H_), 256, 67584>>>(Qh, Kh, mask, attn, rmx);

    // 6. Softmax in place
    softmax_kernel<<<B_ * H_ * S_, 256>>>(attn, rmx);

    // 7. PV
    pv_kernel<<<dim3(S_ / 128, B_ * H_), 256>>>(attn, Vh, ctx);

    // 8. Output projection + residual (HMMA)
    asplit_kernel<<<ASPLIT_G, 256>>>((const float4*)ctx, (uint2*)Ah, (uint2*)Al);
    hmma_gemm<<<gg, 256, GEMM_SMEM>>>(Ah, Al, WTh + 3 * WSZ, WTl + 3 * WSZ, q, out);
}

// round 13
// speedup vs baseline: 1.4339x; 1.0597x over previous
#include <cuda_runtime.h>
#include <cuda_bf16.h>
#include <math.h>
#include <stdint.h>

// ---------------------------------------------------------------------------
// MultiHeadAttention: B=4, S=2048, D_MODEL=1024, HEADS=16, D_K=D_V=64
// Output: concat( out[B,S,1024], attn[B,H,S,S] ) fp32
// All GEMMs (projections, QK^T, PV) on HMMA bf16 hi/lo split-3.
// ---------------------------------------------------------------------------

#define B_   4
#define S_   2048
#define DM   1024
#define H_   16
#define DK   64
#define BS_  (B_ * S_)                 // 8192
#define NROW (B_ * H_ * S_)            // 131072
#define ATTN_OFF ((size_t)BS_ * DM)
#define NEG_INF_F (-1000000000.0f)

// Scratch (static device globals; no runtime allocation)
__device__ __align__(16) __nv_bfloat16 g_WTh[4][DM * DM];
__device__ __align__(16) __nv_bfloat16 g_WTl[4][DM * DM];
__device__ __align__(16) __nv_bfloat16 g_Ah [BS_ * DM];
__device__ __align__(16) __nv_bfloat16 g_Al [BS_ * DM];
__device__ __align__(16) __nv_bfloat16 g_Qsh[BS_ * DM];
__device__ __align__(16) __nv_bfloat16 g_Qsl[BS_ * DM];
__device__ __align__(16) __nv_bfloat16 g_Ksh[BS_ * DM];
__device__ __align__(16) __nv_bfloat16 g_Ksl[BS_ * DM];
__device__ __align__(16) __nv_bfloat16 g_Vsh[BS_ * DM];
__device__ __align__(16) __nv_bfloat16 g_Vsl[BS_ * DM];
__device__ __align__(16) __nv_bfloat16 g_Vth[BS_ * DM];
__device__ __align__(16) __nv_bfloat16 g_Vtl[BS_ * DM];
__device__ __align__(16) __nv_bfloat16 g_Ch [BS_ * DM];
__device__ __align__(16) __nv_bfloat16 g_Cl [BS_ * DM];
__device__ float g_tm  [(size_t)NROW * 16];
__device__ float g_tsc [(size_t)NROW * 16];
__device__ float g_rowM[NROW];
__device__ float g_rowS[NROW];

// ============================ PTX helpers ==================================
__device__ __forceinline__ uint32_t smem_u32(const void* p) {
    uint32_t a;
    asm("{ .reg .u64 t; cvta.to.shared.u64 t, %1; cvt.u32.u64 %0, t; }"
        : "=r"(a) : "l"(p));
    return a;
}
__device__ __forceinline__ void ldmat4(uint32_t* r, uint32_t addr) {
    asm volatile("ldmatrix.sync.aligned.m8n8.x4.shared.b16 {%0,%1,%2,%3}, [%4];"
                 : "=r"(r[0]), "=r"(r[1]), "=r"(r[2]), "=r"(r[3]) : "r"(addr));
}
__device__ __forceinline__ void ldmat2(uint32_t* r, uint32_t addr) {
    asm volatile("ldmatrix.sync.aligned.m8n8.x2.shared.b16 {%0,%1}, [%2];"
                 : "=r"(r[0]), "=r"(r[1]) : "r"(addr));
}
__device__ __forceinline__ void mma_bf16(float* d, const uint32_t* a,
                                         const uint32_t* b) {
    asm volatile(
        "mma.sync.aligned.m16n8k16.row.col.f32.bf16.bf16.f32 "
        "{%0,%1,%2,%3}, {%4,%5,%6,%7}, {%8,%9}, {%0,%1,%2,%3};"
        : "+f"(d[0]), "+f"(d[1]), "+f"(d[2]), "+f"(d[3])
        : "r"(a[0]), "r"(a[1]), "r"(a[2]), "r"(a[3]), "r"(b[0]), "r"(b[1]));
}
__device__ __forceinline__ void cpasync16(uint32_t dst, const void* src) {
    asm volatile("cp.async.cg.shared.global [%0], [%1], 16;"
                 :: "r"(dst), "l"(src));
}
#define CP_COMMIT() asm volatile("cp.async.commit_group;" ::: "memory")
#define CP_WAIT1()  asm volatile("cp.async.wait_group 1;"  ::: "memory")
#define CP_WAIT0()  asm volatile("cp.async.wait_group 0;"  ::: "memory")
__device__ __forceinline__ void sts128(uint32_t addr, uint4 v) {
    asm volatile("st.shared.v4.b32 [%0], {%1,%2,%3,%4};"
                 :: "r"(addr), "r"(v.x), "r"(v.y), "r"(v.z), "r"(v.w) : "memory");
}

union U8  { __nv_bfloat16 h[8]; uint4 u; };
union U4  { __nv_bfloat16 h[4]; uint2 u; };
union U2  { __nv_bfloat16 h[2]; uint32_t u; };

__device__ __forceinline__ void store2_split(__nv_bfloat16* Ch, __nv_bfloat16* Cl,
                                             size_t off, float v0, float v1) {
    U2 hh, ll;
    __nv_bfloat16 h0 = __float2bfloat16(v0), h1 = __float2bfloat16(v1);
    hh.h[0] = h0; hh.h[1] = h1;
    ll.h[0] = __float2bfloat16(v0 - __bfloat162float(h0));
    ll.h[1] = __float2bfloat16(v1 - __bfloat162float(h1));
    *(uint32_t*)(Ch + off) = hh.u;
    *(uint32_t*)(Cl + off) = ll.u;
}

// ---------------------------------------------------------------------------
// Weight transpose + bf16 hi/lo split (optional scale):
//   W[K][N] fp32 -> Th/Tl[N][K] bf16, value*scale
// ---------------------------------------------------------------------------
__global__ void __launch_bounds__(256) wtrans_kernel(
    const float* __restrict__ W, __nv_bfloat16* __restrict__ Th,
    __nv_bfloat16* __restrict__ Tl, float scale)
{
    __shared__ float t[32][33];
    int bx = blockIdx.x << 5;   // n
    int by = blockIdx.y << 5;   // k
    int x = threadIdx.x & 31, y = threadIdx.x >> 5;
    #pragma unroll
    for (int r = 0; r < 32; r += 8)
        t[y + r][x] = W[(size_t)(by + y + r) * DM + bx + x];
    __syncthreads();
    #pragma unroll
    for (int r = 0; r < 32; r += 8) {
        int nl = y + r;
        float v = t[x][nl] * scale;
        __nv_bfloat16 h = __float2bfloat16(v);
        __nv_bfloat16 l = __float2bfloat16(v - __bfloat162float(h));
        size_t o = (size_t)(bx + nl) * DM + by + x;
        Th[o] = h;
        Tl[o] = l;
    }
}

// ---------------------------------------------------------------------------
// Activation split: fp32 -> bf16 hi + lo
// ---------------------------------------------------------------------------
__global__ void __launch_bounds__(256) asplit_kernel(
    const float4* __restrict__ A, uint2* __restrict__ Ah, uint2* __restrict__ Al)
{
    int i = blockIdx.x * 256 + threadIdx.x;
    float4 v = A[i];
    float f[4] = {v.x, v.y, v.z, v.w};
    U4 ph, pl;
    #pragma unroll
    for (int j = 0; j < 4; j++) {
        __nv_bfloat16 h = __float2bfloat16(f[j]);
        ph.h[j] = h;
        pl.h[j] = __float2bfloat16(f[j] - __bfloat162float(h));
    }
    Ah[i] = ph.u;
    Al[i] = pl.u;
}

// ---------------------------------------------------------------------------
// Block-wide sum over 256 threads.
// ---------------------------------------------------------------------------
__device__ __forceinline__ float blk_sum256(float v, float* sbuf) {
    #pragma unroll
    for (int o = 16; o; o >>= 1) v += __shfl_xor_sync(0xffffffffu, v, o);
    int t = threadIdx.x;
    if ((t & 31) == 0) sbuf[t >> 5] = v;
    __syncthreads();
    float r = sbuf[0] + sbuf[1] + sbuf[2] + sbuf[3] +
              sbuf[4] + sbuf[5] + sbuf[6] + sbuf[7];
    __syncthreads();
    return r;
}

// ---------------------------------------------------------------------------
// LayerNorm over rows of 1024, output split directly to bf16 hi/lo.
// ---------------------------------------------------------------------------
__global__ void __launch_bounds__(256) ln_split_kernel(
    const float* __restrict__ x, const float* __restrict__ gamma,
    const float* __restrict__ beta, uint2* __restrict__ Yh, uint2* __restrict__ Yl)
{
    __shared__ float sbuf[8];
    int rowi = blockIdx.x;
    int t = threadIdx.x;
    const float4* xr = (const float4*)(x + (size_t)rowi * DM);
    float4 v = xr[t];
    float s = v.x + v.y + v.z + v.w;
    float tot = blk_sum256(s, sbuf);
    float mean = tot * (1.0f / DM);
    float dx = v.x - mean, dy = v.y - mean, dz = v.z - mean, dw = v.w - mean;
    float s2 = dx*dx + dy*dy + dz*dz + dw*dw;
    float tot2 = blk_sum256(s2, sbuf);
    float rstd = rsqrtf(tot2 * (1.0f / DM) + 1e-6f);
    float4 g  = ((const float4*)gamma)[t];
    float4 bb = ((const float4*)beta)[t];
    float o[4];
    o[0] = dx * rstd * g.x + bb.x;
    o[1] = dy * rstd * g.y + bb.y;
    o[2] = dz * rstd * g.z + bb.z;
    o[3] = dw * rstd * g.w + bb.w;
    U4 ph, pl;
    #pragma unroll
    for (int j = 0; j < 4; j++) {
        __nv_bfloat16 h = __float2bfloat16(o[j]);
        ph.h[j] = h;
        pl.h[j] = __float2bfloat16(o[j] - __bfloat162float(h));
    }
    Yh[rowi * 256 + t] = ph.u;
    Yl[rowi * 256 + t] = pl.u;
}

// ---------------------------------------------------------------------------
// HMMA GEMM: C = (Ah+Al)[8192][1024] @ (Bh+Bl)^T  (+R)
// Output either fp32 C (+R) or split Ch/Cl bf16.
// ---------------------------------------------------------------------------
#define STG_      40
#define ARR_B     (128 * STG_ * 2)        // 10240 bytes per array
#define STAGE_B   (4 * ARR_B)             // 40960
#define GEMM_SMEM (2 * STAGE_B)           // 81920

__global__ void __launch_bounds__(256, 2) hmma_gemm(
    const __nv_bfloat16* __restrict__ Ah, const __nv_bfloat16* __restrict__ Al,
    const __nv_bfloat16* __restrict__ Bh, const __nv_bfloat16* __restrict__ Bl,
    const float* __restrict__ R, float* __restrict__ C,
    __nv_bfloat16* __restrict__ Ch, __nv_bfloat16* __restrict__ Cl)
{
    extern __shared__ char dynsm[];
    uint32_t sbase = smem_u32(dynsm);

    int tid = threadIdx.x, lane = tid & 31, wid = tid >> 5;
    int wm = (wid & 1) << 6;
    int wn = (wid >> 1) << 5;
    int bm = blockIdx.y << 7, bn = blockIdx.x << 7;

    float acc[4][4][4];
    #pragma unroll
    for (int mt = 0; mt < 4; mt++)
        #pragma unroll
        for (int nt = 0; nt < 4; nt++)
            #pragma unroll
            for (int e = 0; e < 4; e++) acc[mt][nt][e] = 0.0f;

    int l_row0 = (tid << 1) >> 2;
    int l_seg0 = (tid << 1) & 3;
    int l_row1 = ((tid << 1) | 1) >> 2;
    int l_seg1 = ((tid << 1) | 1) & 3;

    #define LOAD_STAGE(s, kc) do {                                            \
        uint32_t sb_ = sbase + (s) * STAGE_B;                                 \
        int k0_ = (kc) << 5;                                                  \
        uint32_t d0_ = sb_ + l_row0 * 80 + l_seg0 * 16;                       \
        uint32_t d1_ = sb_ + l_row1 * 80 + l_seg1 * 16;                       \
        const __nv_bfloat16* a0_ = Ah + (size_t)(bm + l_row0) * DM + k0_ + l_seg0 * 8; \
        const __nv_bfloat16* a1_ = Ah + (size_t)(bm + l_row1) * DM + k0_ + l_seg1 * 8; \
        const __nv_bfloat16* b0_ = Bh + (size_t)(bn + l_row0) * DM + k0_ + l_seg0 * 8; \
        const __nv_bfloat16* b1_ = Bh + (size_t)(bn + l_row1) * DM + k0_ + l_seg1 * 8; \
        cpasync16(d0_,              a0_);                                     \
        cpasync16(d0_ + ARR_B,      a0_ + (Al - Ah));                         \
        cpasync16(d0_ + 2 * ARR_B,  b0_);                                     \
        cpasync16(d0_ + 3 * ARR_B,  b0_ + (Bl - Bh));                         \
        cpasync16(d1_,              a1_);                                     \
        cpasync16(d1_ + ARR_B,      a1_ + (Al - Ah));                         \
        cpasync16(d1_ + 2 * ARR_B,  b1_);                                     \
        cpasync16(d1_ + 3 * ARR_B,  b1_ + (Bl - Bh));                         \
        CP_COMMIT();                                                          \
    } while (0)

    LOAD_STAGE(0, 0);

    const int NK = DM / 32;
    for (int kc = 0; kc < NK; kc++) {
        int s = kc & 1;
        if (kc + 1 < NK) {
            LOAD_STAGE(s ^ 1, kc + 1);
            CP_WAIT1();
        } else {
            CP_WAIT0();
        }
        __syncthreads();

        uint32_t sb = sbase + s * STAGE_B;
        #pragma unroll
        for (int ks = 0; ks < 2; ks++) {
            int kb = ks << 4;
            uint32_t ah[4][4], al[4][4];
            uint32_t a_addr = sb +
                (((wm + (lane & 15)) * STG_ + kb + ((lane >> 4) << 3)) << 1);
            #pragma unroll
            for (int mt = 0; mt < 4; mt++) {
                ldmat4(ah[mt], a_addr + mt * (16 * STG_ * 2));
                ldmat4(al[mt], a_addr + mt * (16 * STG_ * 2) + ARR_B);
            }
            uint32_t b_addr = sb + 2 * ARR_B +
                (((wn + (lane & 7)) * STG_ + kb + (((lane >> 3) & 1) << 3)) << 1);
            #pragma unroll
            for (int nt = 0; nt < 4; nt++) {
                uint32_t bh[2], bl[2];
                ldmat2(bh, b_addr + nt * (8 * STG_ * 2));
                ldmat2(bl, b_addr + nt * (8 * STG_ * 2) + ARR_B);
                #pragma unroll
                for (int mt = 0; mt < 4; mt++) {
                    mma_bf16(acc[mt][nt], ah[mt], bh);
                    mma_bf16(acc[mt][nt], ah[mt], bl);
                    mma_bf16(acc[mt][nt], al[mt], bh);
                }
            }
        }
        __syncthreads();
    }

    int rq = lane >> 2, cq = (lane & 3) << 1;
    if (C) {
        #pragma unroll
        for (int mt = 0; mt < 4; mt++) {
            int r0 = bm + wm + (mt << 4) + rq;
            #pragma unroll
            for (int nt = 0; nt < 4; nt++) {
                int c = bn + wn + (nt << 3) + cq;
                float2 v0 = make_float2(acc[mt][nt][0], acc[mt][nt][1]);
                float2 v1 = make_float2(acc[mt][nt][2], acc[mt][nt][3]);
                if (R) {
                    float2 r0v = *(const float2*)(R + (size_t)r0 * DM + c);
                    float2 r1v = *(const float2*)(R + (size_t)(r0 + 8) * DM + c);
                    v0.x += r0v.x; v0.y += r0v.y;
                    v1.x += r1v.x; v1.y += r1v.y;
                }
                *(float2*)(C + (size_t)r0 * DM + c) = v0;
                *(float2*)(C + (size_t)(r0 + 8) * DM + c) = v1;
            }
        }
    } else {
        #pragma unroll
        for (int mt = 0; mt < 4; mt++) {
            int r0 = bm + wm + (mt << 4) + rq;
            #pragma unroll
            for (int nt = 0; nt < 4; nt++) {
                int c = bn + wn + (nt << 3) + cq;
                store2_split(Ch, Cl, (size_t)r0 * DM + c,
                             acc[mt][nt][0], acc[mt][nt][1]);
                store2_split(Ch, Cl, (size_t)(r0 + 8) * DM + c,
                             acc[mt][nt][2], acc[mt][nt][3]);
            }
        }
    }
    #undef LOAD_STAGE
}

// ---------------------------------------------------------------------------
// V transpose: Vs hi/lo [8192][1024] -> Vt hi/lo [bh][64 d][2048 s]
// ---------------------------------------------------------------------------
__global__ void __launch_bounds__(256) vtrans_kernel(
    const __nv_bfloat16* __restrict__ Vh, const __nv_bfloat16* __restrict__ Vl,
    __nv_bfloat16* __restrict__ Th, __nv_bfloat16* __restrict__ Tl)
{
    __shared__ __nv_bfloat16 th[32][33], tl[32][33];
    int rt = blockIdx.x << 5;
    int ct = blockIdx.y << 5;
    int x = threadIdx.x & 31, y = threadIdx.x >> 5;
    #pragma unroll
    for (int r = 0; r < 32; r += 8) {
        th[y + r][x] = Vh[(size_t)(rt + y + r) * DM + ct + x];
        tl[y + r][x] = Vl[(size_t)(rt + y + r) * DM + ct + x];
    }
    __syncthreads();
    int b = rt >> 11;
    int s0 = rt & 2047;
    #pragma unroll
    for (int r = 0; r < 32; r += 8) {
        int col = ct + y + r;
        int h = col >> 6, d = col & 63;
        size_t o = ((size_t)(b * H_ + h) * DK + d) * S_ + s0 + x;
        Th[o] = th[x][y + r];
        Tl[o] = tl[x][y + r];
    }
}

// ---------------------------------------------------------------------------
// scores2: per block 128 q-rows x full 2048 k.  Warp owns 16 rows x 128 k/tile.
// Writes E = exp(s - m_t) to attn, m_t per (row,tile), final (M, sigma).
// Dyn smem: Qh|Ql (18432 ea) + Kh[2]|Kl[2] (18432 ea) = 110592 B.
// ---------------------------------------------------------------------------
__global__ void __launch_bounds__(256, 2) scores2_kernel(
    const __nv_bfloat16* __restrict__ Qsh, const __nv_bfloat16* __restrict__ Qsl,
    const __nv_bfloat16* __restrict__ Ksh, const __nv_bfloat16* __restrict__ Ksl,
    const int* __restrict__ mask, float* __restrict__ attn,
    float* __restrict__ tm, float* __restrict__ rowM, float* __restrict__ rowS)
{
    extern __shared__ char dsm[];
    uint32_t sb = smem_u32(dsm);
    const uint32_t sQh = sb;                 // 18432
    const uint32_t sQl = sb + 18432;
    const uint32_t sKh = sb + 36864;         // 2 stages x 18432
    const uint32_t sKl = sb + 73728;         // 2 stages x 18432
    __shared__ int msk[2][128];

    int tid = threadIdx.x, lane = tid & 31, wid = tid >> 5;
    int bh = blockIdx.y, b = bh >> 4, h = bh & 15;
    int q0 = blockIdx.x << 7;
    int ql = lane >> 2, cq = (lane & 3) << 1;

    // Q tile load (once): 128 rows x 64 k, hi+lo
    #pragma unroll
    for (int i = 0; i < 4; i++) {
        int sidx = tid + (i << 8);
        int row = sidx >> 3, off = (sidx & 7) << 3;
        uint32_t d = (uint32_t)((row * 72 + off) << 1);
        size_t go = (size_t)(b * S_ + q0 + row) * DM + h * DK + off;
        cpasync16(sQh + d, Qsh + go);
        cpasync16(sQl + d, Qsl + go);
    }

    #define LOADK(st, kt) do {                                                \
        int kb_ = (kt) << 7;                                                  \
        if (tid < 128) msk[st][tid] = mask[b * S_ + kb_ + tid];               \
        _Pragma("unroll")                                                     \
        for (int i = 0; i < 4; i++) {                                         \
            int sidx = tid + (i << 8);                                        \
            int row = sidx >> 3, off = (sidx & 7) << 3;                       \
            uint32_t d = (uint32_t)(((st) * 18432) + ((row * 72 + off) << 1));\
            size_t go = (size_t)(b * S_ + kb_ + row) * DM + h * DK + off;     \
            cpasync16(sKh + d, Ksh + go);                                     \
            cpasync16(sKl + d, Ksl + go);                                     \
        }                                                                     \
    } while (0)

    LOADK(0, 0);
    CP_COMMIT();

    float m0 = -3.0e38f, m1 = -3.0e38f, sg0 = 0.0f, sg1 = 0.0f;
    int wrow = (wid << 4) + ql;
    size_t R0 = (size_t)bh * S_ + q0 + wrow;

    for (int kt = 0; kt < 16; kt++) {
        int st = kt & 1;
        if (kt + 1 < 16) {
            LOADK(st ^ 1, kt + 1);
            CP_COMMIT();
            CP_WAIT1();
        } else {
            CP_WAIT0();
        }
        __syncthreads();

        float acc[16][4];
        #pragma unroll
        for (int nt = 0; nt < 16; nt++)
            #pragma unroll
            for (int e = 0; e < 4; e++) acc[nt][e] = 0.0f;

        uint32_t kbase = sKh + st * 18432;
        #pragma unroll
        for (int ks = 0; ks < 4; ks++) {
            uint32_t ah4[4], al4[4];
            uint32_t aaddr = sQh +
                ((((wid << 4) + (lane & 15)) * 72 + (ks << 4) + ((lane >> 4) << 3)) << 1);
            ldmat4(ah4, aaddr);
            ldmat4(al4, aaddr + 18432);
            #pragma unroll
            for (int p = 0; p < 8; p++) {
                uint32_t bh4[4], bl4[4];
                uint32_t baddr = kbase +
                    ((((p << 4) + (lane & 7) + ((lane >> 4) << 3)) * 72 +
                      (ks << 4) + (((lane >> 3) & 1) << 3)) << 1);
                ldmat4(bh4, baddr);
                ldmat4(bl4, baddr + 36864);   // sKl - sKh
                mma_bf16(acc[2 * p],     ah4, bh4);
                mma_bf16(acc[2 * p],     ah4, bl4);
                mma_bf16(acc[2 * p],     al4, bh4);
                mma_bf16(acc[2 * p + 1], ah4, bh4 + 2);
                mma_bf16(acc[2 * p + 1], ah4, bl4 + 2);
                mma_bf16(acc[2 * p + 1], al4, bh4 + 2);
            }
        }

        // mask + tile max
        float mx0 = -3.0e38f, mx1 = -3.0e38f;
        #pragma unroll
        for (int nt = 0; nt < 16; nt++) {
            int c0 = (nt << 3) + cq;
            bool k0m = msk[st][c0] != 0;
            bool k1m = msk[st][c0 + 1] != 0;
            acc[nt][0] = k0m ? acc[nt][0] : NEG_INF_F;
            acc[nt][1] = k1m ? acc[nt][1] : NEG_INF_F;
            acc[nt][2] = k0m ? acc[nt][2] : NEG_INF_F;
            acc[nt][3] = k1m ? acc[nt][3] : NEG_INF_F;
            mx0 = fmaxf(mx0, fmaxf(acc[nt][0], acc[nt][1]));
            mx1 = fmaxf(mx1, fmaxf(acc[nt][2], acc[nt][3]));
        }
        mx0 = fmaxf(mx0, __shfl_xor_sync(0xffffffffu, mx0, 1));
        mx0 = fmaxf(mx0, __shfl_xor_sync(0xffffffffu, mx0, 2));
        mx1 = fmaxf(mx1, __shfl_xor_sync(0xffffffffu, mx1, 1));
        mx1 = fmaxf(mx1, __shfl_xor_sync(0xffffffffu, mx1, 2));
        float mp0 = m0; m0 = fmaxf(m0, mx0); sg0 *= __expf(mp0 - m0);
        float mp1 = m1; m1 = fmaxf(m1, mx1); sg1 *= __expf(mp1 - m1);

        int kb = kt << 7;
        float* o0 = attn + R0 * S_ + kb;
        float* o1 = attn + (R0 + 8) * S_ + kb;
        #pragma unroll
        for (int nt = 0; nt < 16; nt++) {
            int c0 = (nt << 3) + cq;
            float e0 = __expf(acc[nt][0] - m0), e1 = __expf(acc[nt][1] - m0);
            float e2 = __expf(acc[nt][2] - m1), e3 = __expf(acc[nt][3] - m1);
            sg0 += e0 + e1;
            sg1 += e2 + e3;
            *(float2*)(o0 + c0) = make_float2(e0, e1);
            *(float2*)(o1 + c0) = make_float2(e2, e3);
        }
        if ((lane & 3) == 0) {
            tm[R0 * 16 + kt]       = m0;
            tm[(R0 + 8) * 16 + kt] = m1;
        }
        __syncthreads();
    }

    sg0 += __shfl_xor_sync(0xffffffffu, sg0, 1);
    sg0 += __shfl_xor_sync(0xffffffffu, sg0, 2);
    sg1 += __shfl_xor_sync(0xffffffffu, sg1, 1);
    sg1 += __shfl_xor_sync(0xffffffffu, sg1, 2);
    if ((lane & 3) == 0) {
        rowM[R0] = m0;      rowS[R0] = sg0;
        rowM[R0 + 8] = m1;  rowS[R0 + 8] = sg1;
    }
    #undef LOADK
}

// ---------------------------------------------------------------------------
// finalize: scale[row][tile] = exp(m_t - M) / sigma
// ---------------------------------------------------------------------------
__global__ void __launch_bounds__(256) fin_kernel(
    const float* __restrict__ tm, const float* __restrict__ rM,
    const float* __restrict__ rS, float* __restrict__ tsc)
{
    int i = blockIdx.x * 256 + threadIdx.x;
    int R = i >> 4;
    tsc[i] = __expf(tm[i] - rM[R]) / rS[R];
}

// ---------------------------------------------------------------------------
// normPV: p = E * scale (write probs in place), ctx = P @ V via HMMA split-3,
// ctx written as bf16 hi/lo for the Wo GEMM.
// Dyn smem: Ph|Pl (34816 ea) + Vh|Vl (17408 ea) = 104448 B.
// ---------------------------------------------------------------------------
__global__ void __launch_bounds__(256, 2) normpv_kernel(
    float* __restrict__ attn, const float* __restrict__ tsc,
    const __nv_bfloat16* __restrict__ Vth, const __nv_bfloat16* __restrict__ Vtl,
    __nv_bfloat16* __restrict__ Ch, __nv_bfloat16* __restrict__ Cl)
{
    extern __shared__ char dsm[];
    uint32_t sb = smem_u32(dsm);
    const uint32_t sPh = sb;                 // 34816
    const uint32_t sPl = sb + 34816;
    const uint32_t sVh = sb + 69632;         // 17408
    const uint32_t sVl = sb + 87040;

    int tid = threadIdx.x, lane = tid & 31, wid = tid >> 5;
    int bh = blockIdx.y, b = bh >> 4, h = bh & 15;
    int q0 = blockIdx.x << 7;
    int wm = (wid & 3) << 5, wn = (wid >> 2) << 5;
    int rq = lane >> 2, cq = (lane & 3) << 1;

    float acc[2][4][4];
    #pragma unroll
    for (int mt = 0; mt < 2; mt++)
        #pragma unroll
        for (int nt = 0; nt < 4; nt++)
            #pragma unroll
            for (int e = 0; e < 4; e++) acc[mt][nt][e] = 0.0f;

    int pr = tid >> 1;
    int phalf = (tid & 1) << 6;
    size_t Rr = (size_t)bh * S_ + q0 + pr;

    for (int kt = 0; kt < 16; kt++) {
        int kb = kt << 7;
        // V tile async
        #pragma unroll
        for (int i = 0; i < 4; i++) {
            int sidx = tid + (i << 8);
            int d = sidx >> 4, off = (sidx & 15) << 3;
            uint32_t dst = (uint32_t)((d * 136 + off) << 1);
            size_t go = ((size_t)bh * DK + d) * S_ + kb + off;
            cpasync16(sVh + dst, Vth + go);
            cpasync16(sVl + dst, Vtl + go);
        }
        CP_COMMIT();

        // P: read E, scale -> p, write back, split into smem
        float sc = tsc[Rr * 16 + kt];
        float* erow = attn + Rr * S_ + kb + phalf;
        #pragma unroll
        for (int g = 0; g < 8; g++) {
            float4 vA = *(const float4*)(erow + (g << 3));
            float4 vB = *(const float4*)(erow + (g << 3) + 4);
            float pv[8] = {vA.x * sc, vA.y * sc, vA.z * sc, vA.w * sc,
                           vB.x * sc, vB.y * sc, vB.z * sc, vB.w * sc};
            *(float4*)(erow + (g << 3))     = make_float4(pv[0], pv[1], pv[2], pv[3]);
            *(float4*)(erow + (g << 3) + 4) = make_float4(pv[4], pv[5], pv[6], pv[7]);
            U8 Hh, Ll;
            #pragma unroll
            for (int j = 0; j < 8; j++) {
                __nv_bfloat16 hh = __float2bfloat16(pv[j]);
                Hh.h[j] = hh;
                Ll.h[j] = __float2bfloat16(pv[j] - __bfloat162float(hh));
            }
            uint32_t doff = (uint32_t)((pr * 136 + phalf + (g << 3)) << 1);
            sts128(sPh + doff, Hh.u);
            sts128(sPl + doff, Ll.u);
        }
        CP_WAIT0();
        __syncthreads();

        #pragma unroll
        for (int ks = 0; ks < 8; ks++) {
            uint32_t ah4[2][4], al4[2][4];
            #pragma unroll
            for (int mt = 0; mt < 2; mt++) {
                uint32_t aaddr = sPh +
                    (((wm + (mt << 4) + (lane & 15)) * 136 +
                      (ks << 4) + ((lane >> 4) << 3)) << 1);
                ldmat4(ah4[mt], aaddr);
                ldmat4(al4[mt], aaddr + 34816);
            }
            #pragma unroll
            for (int p = 0; p < 2; p++) {
                uint32_t bh4[4], bl4[4];
                uint32_t baddr = sVh +
                    (((wn + (p << 4) + (lane & 7) + ((lane >> 4) << 3)) * 136 +
                      (ks << 4) + (((lane >> 3) & 1) << 3)) << 1);
                ldmat4(bh4, baddr);
                ldmat4(bl4, baddr + 17408);
                #pragma unroll
                for (int mt = 0; mt < 2; mt++) {
                    mma_bf16(acc[mt][2 * p],     ah4[mt], bh4);
                    mma_bf16(acc[mt][2 * p],     ah4[mt], bl4);
                    mma_bf16(acc[mt][2 * p],     al4[mt], bh4);
                    mma_bf16(acc[mt][2 * p + 1], ah4[mt], bh4 + 2);
                    mma_bf16(acc[mt][2 * p + 1], ah4[mt], bl4 + 2);
                    mma_bf16(acc[mt][2 * p + 1], al4[mt], bh4 + 2);
                }
            }
        }
        __syncthreads();
    }

    // ctx epilogue -> bf16 hi/lo [s][1024]
    #pragma unroll
    for (int mt = 0; mt < 2; mt++) {
        int row = b * S_ + q0 + wm + (mt << 4) + rq;
        #pragma unroll
        for (int nt = 0; nt < 4; nt++) {
            int col = h * DK + wn + (nt << 3) + cq;
            store2_split(Ch, Cl, (size_t)row * DM + col,
                         acc[mt][nt][0], acc[mt][nt][1]);
            store2_split(Ch, Cl, (size_t)(row + 8) * DM + col,
                         acc[mt][nt][2], acc[mt][nt][3]);
        }
    }
}

// ---------------------------------------------------------------------------
extern "C" void kernel_launch(void* const* d_in, const int* in_sizes, int n_in,
                              void* d_out, int out_size)
{
    const float* q    = (const float*)d_in[0];
    const float* k    = (const float*)d_in[1];
    const float* v    = (const float*)d_in[2];
    const int*   mask = (const int*)  d_in[3];
    const float* Wq   = (const float*)d_in[4];
    const float* Wk   = (const float*)d_in[5];
    const float* Wv   = (const float*)d_in[6];
    const float* Wo   = (const float*)d_in[7];
    const float* lg   = (const float*)d_in[8];
    const float* lb   = (const float*)d_in[9];

    float* out  = (float*)d_out;
    float* attn = out + ATTN_OFF;

    __nv_bfloat16 *WTh, *WTl, *Ah, *Al, *Qsh, *Qsl, *Ksh, *Ksl, *Vsh, *Vsl,
                  *Vth, *Vtl, *Ch, *Cl;
    float *tm, *tsc, *rM, *rS;
    cudaGetSymbolAddress((void**)&WTh, g_WTh);
    cudaGetSymbolAddress((void**)&WTl, g_WTl);
    cudaGetSymbolAddress((void**)&Ah,  g_Ah);
    cudaGetSymbolAddress((void**)&Al,  g_Al);
    cudaGetSymbolAddress((void**)&Qsh, g_Qsh);
    cudaGetSymbolAddress((void**)&Qsl, g_Qsl);
    cudaGetSymbolAddress((void**)&Ksh, g_Ksh);
    cudaGetSymbolAddress((void**)&Ksl, g_Ksl);
    cudaGetSymbolAddress((void**)&Vsh, g_Vsh);
    cudaGetSymbolAddress((void**)&Vsl, g_Vsl);
    cudaGetSymbolAddress((void**)&Vth, g_Vth);
    cudaGetSymbolAddress((void**)&Vtl, g_Vtl);
    cudaGetSymbolAddress((void**)&Ch,  g_Ch);
    cudaGetSymbolAddress((void**)&Cl,  g_Cl);
    cudaGetSymbolAddress((void**)&tm,  g_tm);
    cudaGetSymbolAddress((void**)&tsc, g_tsc);
    cudaGetSymbolAddress((void**)&rM,  g_rowM);
    cudaGetSymbolAddress((void**)&rS,  g_rowS);

    cudaFuncSetAttribute(hmma_gemm,
                         cudaFuncAttributeMaxDynamicSharedMemorySize, GEMM_SMEM);
    cudaFuncSetAttribute(scores2_kernel,
                         cudaFuncAttributeMaxDynamicSharedMemorySize, 110592);
    cudaFuncSetAttribute(normpv_kernel,
                         cudaFuncAttributeMaxDynamicSharedMemorySize, 104448);

    const int WSZ = DM * DM;
    dim3 gt(32, 32);

    // 0. Weight transpose + split (Wq folded with 1/sqrt(DK) = 0.125)
    wtrans_kernel<<<gt, 256>>>(Wq, WTh + 0 * WSZ, WTl + 0 * WSZ, 0.125f);
    wtrans_kernel<<<gt, 256>>>(Wk, WTh + 1 * WSZ, WTl + 1 * WSZ, 1.0f);
    wtrans_kernel<<<gt, 256>>>(Wv, WTh + 2 * WSZ, WTl + 2 * WSZ, 1.0f);
    wtrans_kernel<<<gt, 256>>>(Wo, WTh + 3 * WSZ, WTl + 3 * WSZ, 1.0f);

    // 1. LayerNorm(q) -> split
    ln_split_kernel<<<BS_, 256>>>(q, lg, lb, (uint2*)Ah, (uint2*)Al);

    const int ASPLIT_G = BS_ * DM / 4 / 256;
    dim3 gg(DM / 128, BS_ / 128);

    // 2-4. Projections (outputs split bf16)
    hmma_gemm<<<gg, 256, GEMM_SMEM>>>(Ah, Al, WTh + 0 * WSZ, WTl + 0 * WSZ,
                                      nullptr, nullptr, Qsh, Qsl);
    asplit_kernel<<<ASPLIT_G, 256>>>((const float4*)k, (uint2*)Ah, (uint2*)Al);
    hmma_gemm<<<gg, 256, GEMM_SMEM>>>(Ah, Al, WTh + 1 * WSZ, WTl + 1 * WSZ,
                                      nullptr, nullptr, Ksh, Ksl);
    asplit_kernel<<<ASPLIT_G, 256>>>((const float4*)v, (uint2*)Ah, (uint2*)Al);
    hmma_gemm<<<gg, 256, GEMM_SMEM>>>(Ah, Al, WTh + 2 * WSZ, WTl + 2 * WSZ,
                                      nullptr, nullptr, Vsh, Vsl);

    // 5. V transpose to [bh][d][s]
    vtrans_kernel<<<dim3(BS_ / 32, DM / 32), 256>>>(Vsh, Vsl, Vth, Vtl);

    // 6. Scores: E = exp(s - m_t), online (m, sigma), m_t per tile
    scores2_kernel<<<dim3(S_ / 128, B_ * H_), 256, 110592>>>(
        Qsh, Qsl, Ksh, Ksl, mask, attn, tm, rM, rS);

    // 7. Per-(row,tile) scales
    fin_kernel<<<(NROW * 16) / 256, 256>>>(tm, rM, rS, tsc);

    // 8. Normalize probs in place + PV (ctx split bf16)
    normpv_kernel<<<dim3(S_ / 128, B_ * H_), 256, 104448>>>(
        attn, tsc, Vth, Vtl, Ch, Cl);

    // 9. Output projection + residual
    hmma_gemm<<<gg, 256, GEMM_SMEM>>>(Ch, Cl, WTh + 3 * WSZ, WTl + 3 * WSZ,
                                      q, out, nullptr, nullptr);
}

// round 14
// speedup vs baseline: 2.0078x; 1.4002x over previous
#include <cuda_runtime.h>
#include <cuda_bf16.h>
#include <math.h>
#include <stdint.h>

// ---------------------------------------------------------------------------
// MultiHeadAttention: B=4, S=2048, D_MODEL=1024, HEADS=16, D_K=D_V=64
// Output: concat( out[B,S,1024], attn[B,H,S,S] ) fp32
// All GEMMs on HMMA bf16 hi/lo split-3 (mma.sync m16n8k16).
// ---------------------------------------------------------------------------

#define B_   4
#define S_   2048
#define DM   1024
#define H_   16
#define DK   64
#define BS_  (B_ * S_)                 // 8192
#define NROW (B_ * H_ * S_)            // 131072
#define NTILE 32                        // 64-col score tiles per row
#define ATTN_OFF ((size_t)BS_ * DM)
#define NEG_INF_F (-1000000000.0f)

// Scratch (static device globals; no runtime allocation)
__device__ __align__(16) __nv_bfloat16 g_WTh[4][DM * DM];
__device__ __align__(16) __nv_bfloat16 g_WTl[4][DM * DM];
__device__ __align__(16) __nv_bfloat16 g_Ah [BS_ * DM];
__device__ __align__(16) __nv_bfloat16 g_Al [BS_ * DM];
__device__ __align__(16) __nv_bfloat16 g_Qsh[BS_ * DM];
__device__ __align__(16) __nv_bfloat16 g_Qsl[BS_ * DM];
__device__ __align__(16) __nv_bfloat16 g_Ksh[BS_ * DM];
__device__ __align__(16) __nv_bfloat16 g_Ksl[BS_ * DM];
__device__ __align__(16) __nv_bfloat16 g_Vsh[BS_ * DM];
__device__ __align__(16) __nv_bfloat16 g_Vsl[BS_ * DM];
__device__ __align__(16) __nv_bfloat16 g_Vth[BS_ * DM];
__device__ __align__(16) __nv_bfloat16 g_Vtl[BS_ * DM];
__device__ __align__(16) __nv_bfloat16 g_Ch [BS_ * DM];
__device__ __align__(16) __nv_bfloat16 g_Cl [BS_ * DM];
__device__ float g_tm  [(size_t)NROW * NTILE];
__device__ float g_tsc [(size_t)NROW * NTILE];
__device__ float g_rowM[NROW];
__device__ float g_rowS[NROW];

// ============================ PTX helpers ==================================
__device__ __forceinline__ uint32_t smem_u32(const void* p) {
    uint32_t a;
    asm("{ .reg .u64 t; cvta.to.shared.u64 t, %1; cvt.u32.u64 %0, t; }"
        : "=r"(a) : "l"(p));
    return a;
}
__device__ __forceinline__ void ldmat4(uint32_t* r, uint32_t addr) {
    asm volatile("ldmatrix.sync.aligned.m8n8.x4.shared.b16 {%0,%1,%2,%3}, [%4];"
                 : "=r"(r[0]), "=r"(r[1]), "=r"(r[2]), "=r"(r[3]) : "r"(addr));
}
__device__ __forceinline__ void ldmat2(uint32_t* r, uint32_t addr) {
    asm volatile("ldmatrix.sync.aligned.m8n8.x2.shared.b16 {%0,%1}, [%2];"
                 : "=r"(r[0]), "=r"(r[1]) : "r"(addr));
}
__device__ __forceinline__ void mma_bf16(float* d, const uint32_t* a,
                                         const uint32_t* b) {
    asm volatile(
        "mma.sync.aligned.m16n8k16.row.col.f32.bf16.bf16.f32 "
        "{%0,%1,%2,%3}, {%4,%5,%6,%7}, {%8,%9}, {%0,%1,%2,%3};"
        : "+f"(d[0]), "+f"(d[1]), "+f"(d[2]), "+f"(d[3])
        : "r"(a[0]), "r"(a[1]), "r"(a[2]), "r"(a[3]), "r"(b[0]), "r"(b[1]));
}
__device__ __forceinline__ void cpasync16(uint32_t dst, const void* src) {
    asm volatile("cp.async.cg.shared.global [%0], [%1], 16;"
                 :: "r"(dst), "l"(src));
}
#define CP_COMMIT() asm volatile("cp.async.commit_group;" ::: "memory")
#define CP_WAIT1()  asm volatile("cp.async.wait_group 1;"  ::: "memory")
#define CP_WAIT0()  asm volatile("cp.async.wait_group 0;"  ::: "memory")
__device__ __forceinline__ void sts128(uint32_t addr, uint4 v) {
    asm volatile("st.shared.v4.b32 [%0], {%1,%2,%3,%4};"
                 :: "r"(addr), "r"(v.x), "r"(v.y), "r"(v.z), "r"(v.w) : "memory");
}
__device__ __forceinline__ void sts64(uint32_t addr, uint2 v) {
    asm volatile("st.shared.v2.b32 [%0], {%1,%2};"
                 :: "r"(addr), "r"(v.x), "r"(v.y) : "memory");
}

union U8  { __nv_bfloat16 h[8]; uint4 u; };
union U4  { __nv_bfloat16 h[4]; uint2 u; };
union U2  { __nv_bfloat16 h[2]; uint32_t u; };

__device__ __forceinline__ void store2_split(__nv_bfloat16* Ch, __nv_bfloat16* Cl,
                                             size_t off, float v0, float v1) {
    U2 hh, ll;
    __nv_bfloat16 h0 = __float2bfloat16(v0), h1 = __float2bfloat16(v1);
    hh.h[0] = h0; hh.h[1] = h1;
    ll.h[0] = __float2bfloat16(v0 - __bfloat162float(h0));
    ll.h[1] = __float2bfloat16(v1 - __bfloat162float(h1));
    *(uint32_t*)(Ch + off) = hh.u;
    *(uint32_t*)(Cl + off) = ll.u;
}

// ---------------------------------------------------------------------------
// Weight transpose + bf16 hi/lo split: W[K][N] fp32 -> Th/Tl[N][K] bf16 * scale
// ---------------------------------------------------------------------------
__global__ void __launch_bounds__(256) wtrans_kernel(
    const float* __restrict__ W, __nv_bfloat16* __restrict__ Th,
    __nv_bfloat16* __restrict__ Tl, float scale)
{
    __shared__ float t[32][33];
    int bx = blockIdx.x << 5;
    int by = blockIdx.y << 5;
    int x = threadIdx.x & 31, y = threadIdx.x >> 5;
    #pragma unroll
    for (int r = 0; r < 32; r += 8)
        t[y + r][x] = W[(size_t)(by + y + r) * DM + bx + x];
    __syncthreads();
    #pragma unroll
    for (int r = 0; r < 32; r += 8) {
        int nl = y + r;
        float v = t[x][nl] * scale;
        __nv_bfloat16 h = __float2bfloat16(v);
        __nv_bfloat16 l = __float2bfloat16(v - __bfloat162float(h));
        size_t o = (size_t)(bx + nl) * DM + by + x;
        Th[o] = h;
        Tl[o] = l;
    }
}

// ---------------------------------------------------------------------------
// Activation split: fp32 -> bf16 hi + lo
// ---------------------------------------------------------------------------
__global__ void __launch_bounds__(256) asplit_kernel(
    const float4* __restrict__ A, uint2* __restrict__ Ah, uint2* __restrict__ Al)
{
    int i = blockIdx.x * 256 + threadIdx.x;
    float4 v = A[i];
    float f[4] = {v.x, v.y, v.z, v.w};
    U4 ph, pl;
    #pragma unroll
    for (int j = 0; j < 4; j++) {
        __nv_bfloat16 h = __float2bfloat16(f[j]);
        ph.h[j] = h;
        pl.h[j] = __float2bfloat16(f[j] - __bfloat162float(h));
    }
    Ah[i] = ph.u;
    Al[i] = pl.u;
}

// ---------------------------------------------------------------------------
// Block-wide sum over 256 threads.
// ---------------------------------------------------------------------------
__device__ __forceinline__ float blk_sum256(float v, float* sbuf) {
    #pragma unroll
    for (int o = 16; o; o >>= 1) v += __shfl_xor_sync(0xffffffffu, v, o);
    int t = threadIdx.x;
    if ((t & 31) == 0) sbuf[t >> 5] = v;
    __syncthreads();
    float r = sbuf[0] + sbuf[1] + sbuf[2] + sbuf[3] +
              sbuf[4] + sbuf[5] + sbuf[6] + sbuf[7];
    __syncthreads();
    return r;
}

// ---------------------------------------------------------------------------
// LayerNorm over rows of 1024, output split to bf16 hi/lo.
// ---------------------------------------------------------------------------
__global__ void __launch_bounds__(256) ln_split_kernel(
    const float* __restrict__ x, const float* __restrict__ gamma,
    const float* __restrict__ beta, uint2* __restrict__ Yh, uint2* __restrict__ Yl)
{
    __shared__ float sbuf[8];
    int rowi = blockIdx.x;
    int t = threadIdx.x;
    const float4* xr = (const float4*)(x + (size_t)rowi * DM);
    float4 v = xr[t];
    float s = v.x + v.y + v.z + v.w;
    float tot = blk_sum256(s, sbuf);
    float mean = tot * (1.0f / DM);
    float dx = v.x - mean, dy = v.y - mean, dz = v.z - mean, dw = v.w - mean;
    float s2 = dx*dx + dy*dy + dz*dz + dw*dw;
    float tot2 = blk_sum256(s2, sbuf);
    float rstd = rsqrtf(tot2 * (1.0f / DM) + 1e-6f);
    float4 g  = ((const float4*)gamma)[t];
    float4 bb = ((const float4*)beta)[t];
    float o[4];
    o[0] = dx * rstd * g.x + bb.x;
    o[1] = dy * rstd * g.y + bb.y;
    o[2] = dz * rstd * g.z + bb.z;
    o[3] = dw * rstd * g.w + bb.w;
    U4 ph, pl;
    #pragma unroll
    for (int j = 0; j < 4; j++) {
        __nv_bfloat16 h = __float2bfloat16(o[j]);
        ph.h[j] = h;
        pl.h[j] = __float2bfloat16(o[j] - __bfloat162float(h));
    }
    Yh[rowi * 256 + t] = ph.u;
    Yl[rowi * 256 + t] = pl.u;
}

// ---------------------------------------------------------------------------
// HMMA GEMM: C = (Ah+Al)[8192][1024] @ (Bh+Bl)^T  (+R) -> fp32 or split bf16
// ---------------------------------------------------------------------------
#define STG_      40
#define ARR_B     (128 * STG_ * 2)
#define STAGE_B   (4 * ARR_B)
#define GEMM_SMEM (2 * STAGE_B)

__global__ void __launch_bounds__(256, 2) hmma_gemm(
    const __nv_bfloat16* __restrict__ Ah, const __nv_bfloat16* __restrict__ Al,
    const __nv_bfloat16* __restrict__ Bh, const __nv_bfloat16* __restrict__ Bl,
    const float* __restrict__ R, float* __restrict__ C,
    __nv_bfloat16* __restrict__ Ch, __nv_bfloat16* __restrict__ Cl)
{
    extern __shared__ char dynsm[];
    uint32_t sbase = smem_u32(dynsm);

    int tid = threadIdx.x, lane = tid & 31, wid = tid >> 5;
    int wm = (wid & 1) << 6;
    int wn = (wid >> 1) << 5;
    int bm = blockIdx.y << 7, bn = blockIdx.x << 7;

    float acc[4][4][4];
    #pragma unroll
    for (int mt = 0; mt < 4; mt++)
        #pragma unroll
        for (int nt = 0; nt < 4; nt++)
            #pragma unroll
            for (int e = 0; e < 4; e++) acc[mt][nt][e] = 0.0f;

    int l_row0 = (tid << 1) >> 2;
    int l_seg0 = (tid << 1) & 3;
    int l_row1 = ((tid << 1) | 1) >> 2;
    int l_seg1 = ((tid << 1) | 1) & 3;

    #define LOAD_STAGE(s, kc) do {                                            \
        uint32_t sb_ = sbase + (s) * STAGE_B;                                 \
        int k0_ = (kc) << 5;                                                  \
        uint32_t d0_ = sb_ + l_row0 * 80 + l_seg0 * 16;                       \
        uint32_t d1_ = sb_ + l_row1 * 80 + l_seg1 * 16;                       \
        const __nv_bfloat16* a0_ = Ah + (size_t)(bm + l_row0) * DM + k0_ + l_seg0 * 8; \
        const __nv_bfloat16* a1_ = Ah + (size_t)(bm + l_row1) * DM + k0_ + l_seg1 * 8; \
        const __nv_bfloat16* b0_ = Bh + (size_t)(bn + l_row0) * DM + k0_ + l_seg0 * 8; \
        const __nv_bfloat16* b1_ = Bh + (size_t)(bn + l_row1) * DM + k0_ + l_seg1 * 8; \
        cpasync16(d0_,              a0_);                                     \
        cpasync16(d0_ + ARR_B,      a0_ + (Al - Ah));                         \
        cpasync16(d0_ + 2 * ARR_B,  b0_);                                     \
        cpasync16(d0_ + 3 * ARR_B,  b0_ + (Bl - Bh));                         \
        cpasync16(d1_,              a1_);                                     \
        cpasync16(d1_ + ARR_B,      a1_ + (Al - Ah));                         \
        cpasync16(d1_ + 2 * ARR_B,  b1_);                                     \
        cpasync16(d1_ + 3 * ARR_B,  b1_ + (Bl - Bh));                         \
        CP_COMMIT();                                                          \
    } while (0)

    LOAD_STAGE(0, 0);

    const int NK = DM / 32;
    for (int kc = 0; kc < NK; kc++) {
        int s = kc & 1;
        if (kc + 1 < NK) {
            LOAD_STAGE(s ^ 1, kc + 1);
            CP_WAIT1();
        } else {
            CP_WAIT0();
        }
        __syncthreads();

        uint32_t sb = sbase + s * STAGE_B;
        #pragma unroll
        for (int ks = 0; ks < 2; ks++) {
            int kb = ks << 4;
            uint32_t ah[4][4], al[4][4];
            uint32_t a_addr = sb +
                (((wm + (lane & 15)) * STG_ + kb + ((lane >> 4) << 3)) << 1);
            #pragma unroll
            for (int mt = 0; mt < 4; mt++) {
                ldmat4(ah[mt], a_addr + mt * (16 * STG_ * 2));
                ldmat4(al[mt], a_addr + mt * (16 * STG_ * 2) + ARR_B);
            }
            uint32_t b_addr = sb + 2 * ARR_B +
                (((wn + (lane & 7)) * STG_ + kb + (((lane >> 3) & 1) << 3)) << 1);
            #pragma unroll
            for (int nt = 0; nt < 4; nt++) {
                uint32_t bh[2], bl[2];
                ldmat2(bh, b_addr + nt * (8 * STG_ * 2));
                ldmat2(bl, b_addr + nt * (8 * STG_ * 2) + ARR_B);
                #pragma unroll
                for (int mt = 0; mt < 4; mt++) {
                    mma_bf16(acc[mt][nt], ah[mt], bh);
                    mma_bf16(acc[mt][nt], ah[mt], bl);
                    mma_bf16(acc[mt][nt], al[mt], bh);
                }
            }
        }
        __syncthreads();
    }

    int rq = lane >> 2, cq = (lane & 3) << 1;
    if (C) {
        #pragma unroll
        for (int mt = 0; mt < 4; mt++) {
            int r0 = bm + wm + (mt << 4) + rq;
            #pragma unroll
            for (int nt = 0; nt < 4; nt++) {
                int c = bn + wn + (nt << 3) + cq;
                float2 v0 = make_float2(acc[mt][nt][0], acc[mt][nt][1]);
                float2 v1 = make_float2(acc[mt][nt][2], acc[mt][nt][3]);
                if (R) {
                    float2 r0v = *(const float2*)(R + (size_t)r0 * DM + c);
                    float2 r1v = *(const float2*)(R + (size_t)(r0 + 8) * DM + c);
                    v0.x += r0v.x; v0.y += r0v.y;
                    v1.x += r1v.x; v1.y += r1v.y;
                }
                *(float2*)(C + (size_t)r0 * DM + c) = v0;
                *(float2*)(C + (size_t)(r0 + 8) * DM + c) = v1;
            }
        }
    } else {
        #pragma unroll
        for (int mt = 0; mt < 4; mt++) {
            int r0 = bm + wm + (mt << 4) + rq;
            #pragma unroll
            for (int nt = 0; nt < 4; nt++) {
                int c = bn + wn + (nt << 3) + cq;
                store2_split(Ch, Cl, (size_t)r0 * DM + c,
                             acc[mt][nt][0], acc[mt][nt][1]);
                store2_split(Ch, Cl, (size_t)(r0 + 8) * DM + c,
                             acc[mt][nt][2], acc[mt][nt][3]);
            }
        }
    }
    #undef LOAD_STAGE
}

// ---------------------------------------------------------------------------
// V transpose: Vs hi/lo [8192][1024] -> Vt hi/lo [bh][64 d][2048 s]
// ---------------------------------------------------------------------------
__global__ void __launch_bounds__(256) vtrans_kernel(
    const __nv_bfloat16* __restrict__ Vh, const __nv_bfloat16* __restrict__ Vl,
    __nv_bfloat16* __restrict__ Th, __nv_bfloat16* __restrict__ Tl)
{
    __shared__ __nv_bfloat16 th[32][33], tl[32][33];
    int rt = blockIdx.x << 5;
    int ct = blockIdx.y << 5;
    int x = threadIdx.x & 31, y = threadIdx.x >> 5;
    #pragma unroll
    for (int r = 0; r < 32; r += 8) {
        th[y + r][x] = Vh[(size_t)(rt + y + r) * DM + ct + x];
        tl[y + r][x] = Vl[(size_t)(rt + y + r) * DM + ct + x];
    }
    __syncthreads();
    int b = rt >> 11;
    int s0 = rt & 2047;
    #pragma unroll
    for (int r = 0; r < 32; r += 8) {
        int col = ct + y + r;
        int h = col >> 6, d = col & 63;
        size_t o = ((size_t)(b * H_ + h) * DK + d) * S_ + s0 + x;
        Th[o] = th[x][y + r];
        Tl[o] = tl[x][y + r];
    }
}

// ---------------------------------------------------------------------------
// scores2: per block 128 q-rows x full 2048 k.  Warp owns 16 rows.
// Each 128-col k-tile processed in two 64-col halves (acc[8][4], low reg
// pressure).  Writes E = exp(s - m_t) to attn, m_t per (row, 64-col tile),
// final (M, sigma) per row.
// Dyn smem: Qh|Ql (18432 ea) + Kh[2]|Kl[2] (18432 ea) = 110592 B.
// ---------------------------------------------------------------------------
__global__ void __launch_bounds__(256, 2) scores2_kernel(
    const __nv_bfloat16* __restrict__ Qsh, const __nv_bfloat16* __restrict__ Qsl,
    const __nv_bfloat16* __restrict__ Ksh, const __nv_bfloat16* __restrict__ Ksl,
    const int* __restrict__ mask, float* __restrict__ attn,
    float* __restrict__ tm, float* __restrict__ rowM, float* __restrict__ rowS)
{
    extern __shared__ char dsm[];
    uint32_t sb = smem_u32(dsm);
    const uint32_t sQh = sb;
    const uint32_t sQl = sb + 18432;
    const uint32_t sKh = sb + 36864;
    const uint32_t sKl = sb + 73728;
    __shared__ int msk[2][128];

    int tid = threadIdx.x, lane = tid & 31, wid = tid >> 5;
    int bh = blockIdx.y, b = bh >> 4, h = bh & 15;
    int q0 = blockIdx.x << 7;
    int ql = lane >> 2, cq = (lane & 3) << 1;

    #pragma unroll
    for (int i = 0; i < 4; i++) {
        int sidx = tid + (i << 8);
        int row = sidx >> 3, off = (sidx & 7) << 3;
        uint32_t d = (uint32_t)((row * 72 + off) << 1);
        size_t go = (size_t)(b * S_ + q0 + row) * DM + h * DK + off;
        cpasync16(sQh + d, Qsh + go);
        cpasync16(sQl + d, Qsl + go);
    }

    #define LOADK(st, kt) do {                                                \
        int kb_ = (kt) << 7;                                                  \
        if (tid < 128) msk[st][tid] = mask[b * S_ + kb_ + tid];               \
        _Pragma("unroll")                                                     \
        for (int i = 0; i < 4; i++) {                                         \
            int sidx = tid + (i << 8);                                        \
            int row = sidx >> 3, off = (sidx & 7) << 3;                       \
            uint32_t d = (uint32_t)(((st) * 18432) + ((row * 72 + off) << 1));\
            size_t go = (size_t)(b * S_ + kb_ + row) * DM + h * DK + off;     \
            cpasync16(sKh + d, Ksh + go);                                     \
            cpasync16(sKl + d, Ksl + go);                                     \
        }                                                                     \
    } while (0)

    LOADK(0, 0);
    CP_COMMIT();

    float m0 = -3.0e38f, m1 = -3.0e38f, sg0 = 0.0f, sg1 = 0.0f;
    int wrow = (wid << 4) + ql;
    size_t R0 = (size_t)bh * S_ + q0 + wrow;

    for (int kt = 0; kt < 16; kt++) {
        int st = kt & 1;
        if (kt + 1 < 16) {
            LOADK(st ^ 1, kt + 1);
            CP_COMMIT();
            CP_WAIT1();
        } else {
            CP_WAIT0();
        }
        __syncthreads();

        uint32_t kbase = sKh + st * 18432;
        int kb = kt << 7;

        #pragma unroll
        for (int hf = 0; hf < 2; hf++) {
            float acc[8][4];
            #pragma unroll
            for (int nt = 0; nt < 8; nt++)
                #pragma unroll
                for (int e = 0; e < 4; e++) acc[nt][e] = 0.0f;

            #pragma unroll
            for (int ks = 0; ks < 4; ks++) {
                uint32_t ah4[4], al4[4];
                uint32_t aaddr = sQh +
                    ((((wid << 4) + (lane & 15)) * 72 + (ks << 4) +
                      ((lane >> 4) << 3)) << 1);
                ldmat4(ah4, aaddr);
                ldmat4(al4, aaddr + 18432);
                #pragma unroll
                for (int p = 0; p < 4; p++) {
                    int pp = (hf << 2) + p;
                    uint32_t bh4[4], bl4[4];
                    uint32_t baddr = kbase +
                        ((((pp << 4) + (lane & 7) + ((lane >> 4) << 3)) * 72 +
                          (ks << 4) + (((lane >> 3) & 1) << 3)) << 1);
                    ldmat4(bh4, baddr);
                    ldmat4(bl4, baddr + 36864);
                    mma_bf16(acc[2 * p],     ah4, bh4);
                    mma_bf16(acc[2 * p],     ah4, bl4);
                    mma_bf16(acc[2 * p],     al4, bh4);
                    mma_bf16(acc[2 * p + 1], ah4, bh4 + 2);
                    mma_bf16(acc[2 * p + 1], ah4, bl4 + 2);
                    mma_bf16(acc[2 * p + 1], al4, bh4 + 2);
                }
            }

            // mask + half-tile max
            float mx0 = -3.0e38f, mx1 = -3.0e38f;
            #pragma unroll
            for (int nt = 0; nt < 8; nt++) {
                int c0 = (hf << 6) + (nt << 3) + cq;
                bool k0m = msk[st][c0] != 0;
                bool k1m = msk[st][c0 + 1] != 0;
                acc[nt][0] = k0m ? acc[nt][0] : NEG_INF_F;
                acc[nt][1] = k1m ? acc[nt][1] : NEG_INF_F;
                acc[nt][2] = k0m ? acc[nt][2] : NEG_INF_F;
                acc[nt][3] = k1m ? acc[nt][3] : NEG_INF_F;
                mx0 = fmaxf(mx0, fmaxf(acc[nt][0], acc[nt][1]));
                mx1 = fmaxf(mx1, fmaxf(acc[nt][2], acc[nt][3]));
            }
            mx0 = fmaxf(mx0, __shfl_xor_sync(0xffffffffu, mx0, 1));
            mx0 = fmaxf(mx0, __shfl_xor_sync(0xffffffffu, mx0, 2));
            mx1 = fmaxf(mx1, __shfl_xor_sync(0xffffffffu, mx1, 1));
            mx1 = fmaxf(mx1, __shfl_xor_sync(0xffffffffu, mx1, 2));
            float mp0 = m0; m0 = fmaxf(m0, mx0); sg0 *= __expf(mp0 - m0);
            float mp1 = m1; m1 = fmaxf(m1, mx1); sg1 *= __expf(mp1 - m1);

            float* o0 = attn + R0 * S_ + kb;
            float* o1 = attn + (R0 + 8) * S_ + kb;
            #pragma unroll
            for (int nt = 0; nt < 8; nt++) {
                int c0 = (hf << 6) + (nt << 3) + cq;
                float e0 = __expf(acc[nt][0] - m0), e1 = __expf(acc[nt][1] - m0);
                float e2 = __expf(acc[nt][2] - m1), e3 = __expf(acc[nt][3] - m1);
                sg0 += e0 + e1;
                sg1 += e2 + e3;
                *(float2*)(o0 + c0) = make_float2(e0, e1);
                *(float2*)(o1 + c0) = make_float2(e2, e3);
            }
            if ((lane & 3) == 0) {
                int t2 = (kt << 1) + hf;
                tm[R0 * NTILE + t2]       = m0;
                tm[(R0 + 8) * NTILE + t2] = m1;
            }
        }
        __syncthreads();
    }

    sg0 += __shfl_xor_sync(0xffffffffu, sg0, 1);
    sg0 += __shfl_xor_sync(0xffffffffu, sg0, 2);
    sg1 += __shfl_xor_sync(0xffffffffu, sg1, 1);
    sg1 += __shfl_xor_sync(0xffffffffu, sg1, 2);
    if ((lane & 3) == 0) {
        rowM[R0] = m0;      rowS[R0] = sg0;
        rowM[R0 + 8] = m1;  rowS[R0 + 8] = sg1;
    }
    #undef LOADK
}

// ---------------------------------------------------------------------------
// finalize: scale[row][tile] = exp(m_t - M) / sigma   (NTILE per row)
// ---------------------------------------------------------------------------
__global__ void __launch_bounds__(256) fin_kernel(
    const float* __restrict__ tm, const float* __restrict__ rM,
    const float* __restrict__ rS, float* __restrict__ tsc)
{
    int i = blockIdx.x * 256 + threadIdx.x;
    int R = i >> 5;           // NTILE = 32
    tsc[i] = __expf(tm[i] - rM[R]) / rS[R];
}

// ---------------------------------------------------------------------------
// normPV: p = E * scale (coalesced in-place normalize), ctx = P @ V (HMMA),
// ctx written as bf16 hi/lo.  Warp sweeps 16 rows; lanes cover 128 cols.
// Dyn smem: Ph|Pl (34816 ea) + Vh|Vl (17408 ea) = 104448 B.
// ---------------------------------------------------------------------------
__global__ void __launch_bounds__(256, 2) normpv_kernel(
    float* __restrict__ attn, const float* __restrict__ tsc,
    const __nv_bfloat16* __restrict__ Vth, const __nv_bfloat16* __restrict__ Vtl,
    __nv_bfloat16* __restrict__ Ch, __nv_bfloat16* __restrict__ Cl)
{
    extern __shared__ char dsm[];
    uint32_t sb = smem_u32(dsm);
    const uint32_t sPh = sb;
    const uint32_t sPl = sb + 34816;
    const uint32_t sVh = sb + 69632;
    const uint32_t sVl = sb + 87040;

    int tid = threadIdx.x, lane = tid & 31, wid = tid >> 5;
    int bh = blockIdx.y, b = bh >> 4, h = bh & 15;
    int q0 = blockIdx.x << 7;
    int wm = (wid & 3) << 5, wn = (wid >> 2) << 5;
    int rq = lane >> 2, cq = (lane & 3) << 1;

    float acc[2][4][4];
    #pragma unroll
    for (int mt = 0; mt < 2; mt++)
        #pragma unroll
        for (int nt = 0; nt < 4; nt++)
            #pragma unroll
            for (int e = 0; e < 4; e++) acc[mt][nt][e] = 0.0f;

    size_t Rbase = (size_t)bh * S_ + q0 + (wid << 4);

    for (int kt = 0; kt < 16; kt++) {
        int kb = kt << 7;
        // V tile async
        #pragma unroll
        for (int i = 0; i < 4; i++) {
            int sidx = tid + (i << 8);
            int d = sidx >> 4, off = (sidx & 15) << 3;
            uint32_t dst = (uint32_t)((d * 136 + off) << 1);
            size_t go = ((size_t)bh * DK + d) * S_ + kb + off;
            cpasync16(sVh + dst, Vth + go);
            cpasync16(sVl + dst, Vtl + go);
        }
        CP_COMMIT();

        // P phase: warp sweeps its 16 rows; lanes cover 128 contiguous floats
        #pragma unroll 4
        for (int r = 0; r < 16; r++) {
            int row = (wid << 4) + r;
            size_t Rr = Rbase + r;
            float sc = tsc[Rr * NTILE + (kt << 1) + (lane >> 4)];
            float* erow = attn + Rr * S_ + kb + (lane << 2);
            float4 vv = *(const float4*)erow;
            float p0 = vv.x * sc, p1 = vv.y * sc, p2 = vv.z * sc, p3 = vv.w * sc;
            *(float4*)erow = make_float4(p0, p1, p2, p3);
            U4 hh, ll;
            __nv_bfloat16 b0 = __float2bfloat16(p0);
            __nv_bfloat16 b1 = __float2bfloat16(p1);
            __nv_bfloat16 b2 = __float2bfloat16(p2);
            __nv_bfloat16 b3 = __float2bfloat16(p3);
            hh.h[0] = b0; hh.h[1] = b1; hh.h[2] = b2; hh.h[3] = b3;
            ll.h[0] = __float2bfloat16(p0 - __bfloat162float(b0));
            ll.h[1] = __float2bfloat16(p1 - __bfloat162float(b1));
            ll.h[2] = __float2bfloat16(p2 - __bfloat162float(b2));
            ll.h[3] = __float2bfloat16(p3 - __bfloat162float(b3));
            uint32_t doff = (uint32_t)((row * 136 + (lane << 2)) << 1);
            sts64(sPh + doff, hh.u);
            sts64(sPl + doff, ll.u);
        }
        CP_WAIT0();
        __syncthreads();

        #pragma unroll
        for (int ks = 0; ks < 8; ks++) {
            uint32_t ah4[2][4], al4[2][4];
            #pragma unroll
            for (int mt = 0; mt < 2; mt++) {
                uint32_t aaddr = sPh +
                    (((wm + (mt << 4) + (lane & 15)) * 136 +
                      (ks << 4) + ((lane >> 4) << 3)) << 1);
                ldmat4(ah4[mt], aaddr);
                ldmat4(al4[mt], aaddr + 34816);
            }
            #pragma unroll
            for (int p = 0; p < 2; p++) {
                uint32_t bh4[4], bl4[4];
                uint32_t baddr = sVh +
                    (((wn + (p << 4) + (lane & 7) + ((lane >> 4) << 3)) * 136 +
                      (ks << 4) + (((lane >> 3) & 1) << 3)) << 1);
                ldmat4(bh4, baddr);
                ldmat4(bl4, baddr + 17408);
                #pragma unroll
                for (int mt = 0; mt < 2; mt++) {
                    mma_bf16(acc[mt][2 * p],     ah4[mt], bh4);
                    mma_bf16(acc[mt][2 * p],     ah4[mt], bl4);
                    mma_bf16(acc[mt][2 * p],     al4[mt], bh4);
                    mma_bf16(acc[mt][2 * p + 1], ah4[mt], bh4 + 2);
                    mma_bf16(acc[mt][2 * p + 1], ah4[mt], bl4 + 2);
                    mma_bf16(acc[mt][2 * p + 1], al4[mt], bh4 + 2);
                }
            }
        }
        __syncthreads();
    }

    #pragma unroll
    for (int mt = 0; mt < 2; mt++) {
        int row = b * S_ + q0 + wm + (mt << 4) + rq;
        #pragma unroll
        for (int nt = 0; nt < 4; nt++) {
            int col = h * DK + wn + (nt << 3) + cq;
            store2_split(Ch, Cl, (size_t)row * DM + col,
                         acc[mt][nt][0], acc[mt][nt][1]);
            store2_split(Ch, Cl, (size_t)(row + 8) * DM + col,
                         acc[mt][nt][2], acc[mt][nt][3]);
        }
    }
}

// ---------------------------------------------------------------------------
extern "C" void kernel_launch(void* const* d_in, const int* in_sizes, int n_in,
                              void* d_out, int out_size)
{
    const float* q    = (const float*)d_in[0];
    const float* k    = (const float*)d_in[1];
    const float* v    = (const float*)d_in[2];
    const int*   mask = (const int*)  d_in[3];
    const float* Wq   = (const float*)d_in[4];
    const float* Wk   = (const float*)d_in[5];
    const float* Wv   = (const float*)d_in[6];
    const float* Wo   = (const float*)d_in[7];
    const float* lg   = (const float*)d_in[8];
    const float* lb   = (const float*)d_in[9];

    float* out  = (float*)d_out;
    float* attn = out + ATTN_OFF;

    __nv_bfloat16 *WTh, *WTl, *Ah, *Al, *Qsh, *Qsl, *Ksh, *Ksl, *Vsh, *Vsl,
                  *Vth, *Vtl, *Ch, *Cl;
    float *tm, *tsc, *rM, *rS;
    cudaGetSymbolAddress((void**)&WTh, g_WTh);
    cudaGetSymbolAddress((void**)&WTl, g_WTl);
    cudaGetSymbolAddress((void**)&Ah,  g_Ah);
    cudaGetSymbolAddress((void**)&Al,  g_Al);
    cudaGetSymbolAddress((void**)&Qsh, g_Qsh);
    cudaGetSymbolAddress((void**)&Qsl, g_Qsl);
    cudaGetSymbolAddress((void**)&Ksh, g_Ksh);
    cudaGetSymbolAddress((void**)&Ksl, g_Ksl);
    cudaGetSymbolAddress((void**)&Vsh, g_Vsh);
    cudaGetSymbolAddress((void**)&Vsl, g_Vsl);
    cudaGetSymbolAddress((void**)&Vth, g_Vth);
    cudaGetSymbolAddress((void**)&Vtl, g_Vtl);
    cudaGetSymbolAddress((void**)&Ch,  g_Ch);
    cudaGetSymbolAddress((void**)&Cl,  g_Cl);
    cudaGetSymbolAddress((void**)&tm,  g_tm);
    cudaGetSymbolAddress((void**)&tsc, g_tsc);
    cudaGetSymbolAddress((void**)&rM,  g_rowM);
    cudaGetSymbolAddress((void**)&rS,  g_rowS);

    cudaFuncSetAttribute(hmma_gemm,
                         cudaFuncAttributeMaxDynamicSharedMemorySize, GEMM_SMEM);
    cudaFuncSetAttribute(scores2_kernel,
                         cudaFuncAttributeMaxDynamicSharedMemorySize, 110592);
    cudaFuncSetAttribute(normpv_kernel,
                         cudaFuncAttributeMaxDynamicSharedMemorySize, 104448);

    const int WSZ = DM * DM;
    dim3 gt(32, 32);

    // 0. Weight transpose + split (Wq folded with 1/sqrt(DK) = 0.125)
    wtrans_kernel<<<gt, 256>>>(Wq, WTh + 0 * WSZ, WTl + 0 * WSZ, 0.125f);
    wtrans_kernel<<<gt, 256>>>(Wk, WTh + 1 * WSZ, WTl + 1 * WSZ, 1.0f);
    wtrans_kernel<<<gt, 256>>>(Wv, WTh + 2 * WSZ, WTl + 2 * WSZ, 1.0f);
    wtrans_kernel<<<gt, 256>>>(Wo, WTh + 3 * WSZ, WTl + 3 * WSZ, 1.0f);

    // 1. LayerNorm(q) -> split
    ln_split_kernel<<<BS_, 256>>>(q, lg, lb, (uint2*)Ah, (uint2*)Al);

    const int ASPLIT_G = BS_ * DM / 4 / 256;
    dim3 gg(DM / 128, BS_ / 128);

    // 2-4. Projections (outputs split bf16)
    hmma_gemm<<<gg, 256, GEMM_SMEM>>>(Ah, Al, WTh + 0 * WSZ, WTl + 0 * WSZ,
                                      nullptr, nullptr, Qsh, Qsl);
    asplit_kernel<<<ASPLIT_G, 256>>>((const float4*)k, (uint2*)Ah, (uint2*)Al);
    hmma_gemm<<<gg, 256, GEMM_SMEM>>>(Ah, Al, WTh + 1 * WSZ, WTl + 1 * WSZ,
                                      nullptr, nullptr, Ksh, Ksl);
    asplit_kernel<<<ASPLIT_G, 256>>>((const float4*)v, (uint2*)Ah, (uint2*)Al);
    hmma_gemm<<<gg, 256, GEMM_SMEM>>>(Ah, Al, WTh + 2 * WSZ, WTl + 2 * WSZ,
                                      nullptr, nullptr, Vsh, Vsl);

    // 5. V transpose to [bh][d][s]
    vtrans_kernel<<<dim3(BS_ / 32, DM / 32), 256>>>(Vsh, Vsl, Vth, Vtl);

    // 6. Scores: E = exp(s - m_t) with per-64-col-tile m_t
    scores2_kernel<<<dim3(S_ / 128, B_ * H_), 256, 110592>>>(
        Qsh, Qsl, Ksh, Ksl, mask, attn, tm, rM, rS);

    // 7. Per-(row, 64-col tile) scales
    fin_kernel<<<(NROW * NTILE) / 256, 256>>>(tm, rM, rS, tsc);

    // 8. Normalize probs in place + PV (ctx split bf16)
    normpv_kernel<<<dim3(S_ / 128, B_ * H_), 256, 104448>>>(
        attn, tsc, Vth, Vtl, Ch, Cl);

    // 9. Output projection + residual
    hmma_gemm<<<gg, 256, GEMM_SMEM>>>(Ch, Cl, WTh + 3 * WSZ, WTl + 3 * WSZ,
                                      q, out, nullptr, nullptr);
}

// round 15
// speedup vs baseline: 2.0251x; 1.0087x over previous
#include <cuda_runtime.h>
#include <cuda_bf16.h>
#include <math.h>
#include <stdint.h>

// ---------------------------------------------------------------------------
// MultiHeadAttention: B=4, S=2048, D_MODEL=1024, HEADS=16, D_K=D_V=64
// Output: concat( out[B,S,1024], attn[B,H,S,S] ) fp32
// All GEMMs on HMMA bf16 hi/lo split-3 (mma.sync m16n8k16).
// ---------------------------------------------------------------------------

#define B_   4
#define S_   2048
#define DM   1024
#define H_   16
#define DK   64
#define BS_  (B_ * S_)                 // 8192
#define NROW (B_ * H_ * S_)            // 131072
#define NTILE 32                        // 64-col score tiles per row
#define ATTN_OFF ((size_t)BS_ * DM)
#define NEG_INF_F (-1000000000.0f)

// Scratch (static device globals; no runtime allocation)
__device__ __align__(16) __nv_bfloat16 g_WTh[4][DM * DM];
__device__ __align__(16) __nv_bfloat16 g_WTl[4][DM * DM];
__device__ __align__(16) __nv_bfloat16 g_Ah [BS_ * DM];
__device__ __align__(16) __nv_bfloat16 g_Al [BS_ * DM];
__device__ __align__(16) __nv_bfloat16 g_Qsh[BS_ * DM];
__device__ __align__(16) __nv_bfloat16 g_Qsl[BS_ * DM];
__device__ __align__(16) __nv_bfloat16 g_Ksh[BS_ * DM];
__device__ __align__(16) __nv_bfloat16 g_Ksl[BS_ * DM];
__device__ __align__(16) __nv_bfloat16 g_Vsh[BS_ * DM];
__device__ __align__(16) __nv_bfloat16 g_Vsl[BS_ * DM];
__device__ __align__(16) __nv_bfloat16 g_Vth[BS_ * DM];
__device__ __align__(16) __nv_bfloat16 g_Vtl[BS_ * DM];
__device__ __align__(16) __nv_bfloat16 g_Ch [BS_ * DM];
__device__ __align__(16) __nv_bfloat16 g_Cl [BS_ * DM];
__device__ float g_tm  [(size_t)NROW * NTILE];
__device__ float g_tsc [(size_t)NROW * NTILE];
__device__ float g_rowM[NROW];
__device__ float g_rowS[NROW];

// ============================ PTX helpers ==================================
__device__ __forceinline__ uint32_t smem_u32(const void* p) {
    uint32_t a;
    asm("{ .reg .u64 t; cvta.to.shared.u64 t, %1; cvt.u32.u64 %0, t; }"
        : "=r"(a) : "l"(p));
    return a;
}
__device__ __forceinline__ void ldmat4(uint32_t* r, uint32_t addr) {
    asm volatile("ldmatrix.sync.aligned.m8n8.x4.shared.b16 {%0,%1,%2,%3}, [%4];"
                 : "=r"(r[0]), "=r"(r[1]), "=r"(r[2]), "=r"(r[3]) : "r"(addr));
}
__device__ __forceinline__ void mma_bf16(float* d, const uint32_t* a,
                                         const uint32_t* b) {
    asm volatile(
        "mma.sync.aligned.m16n8k16.row.col.f32.bf16.bf16.f32 "
        "{%0,%1,%2,%3}, {%4,%5,%6,%7}, {%8,%9}, {%0,%1,%2,%3};"
        : "+f"(d[0]), "+f"(d[1]), "+f"(d[2]), "+f"(d[3])
        : "r"(a[0]), "r"(a[1]), "r"(a[2]), "r"(a[3]), "r"(b[0]), "r"(b[1]));
}
__device__ __forceinline__ void cpasync16(uint32_t dst, const void* src) {
    asm volatile("cp.async.cg.shared.global [%0], [%1], 16;"
                 :: "r"(dst), "l"(src));
}
#define CP_COMMIT() asm volatile("cp.async.commit_group;" ::: "memory")
#define CP_WAIT2()  asm volatile("cp.async.wait_group 2;"  ::: "memory")
#define CP_WAIT1()  asm volatile("cp.async.wait_group 1;"  ::: "memory")
#define CP_WAIT0()  asm volatile("cp.async.wait_group 0;"  ::: "memory")
__device__ __forceinline__ void sts64(uint32_t addr, uint2 v) {
    asm volatile("st.shared.v2.b32 [%0], {%1,%2};"
                 :: "r"(addr), "r"(v.x), "r"(v.y) : "memory");
}

union U4  { __nv_bfloat16 h[4]; uint2 u; };
union U2  { __nv_bfloat16 h[2]; uint32_t u; };

__device__ __forceinline__ void store2_split(__nv_bfloat16* Ch, __nv_bfloat16* Cl,
                                             size_t off, float v0, float v1) {
    U2 hh, ll;
    __nv_bfloat16 h0 = __float2bfloat16(v0), h1 = __float2bfloat16(v1);
    hh.h[0] = h0; hh.h[1] = h1;
    ll.h[0] = __float2bfloat16(v0 - __bfloat162float(h0));
    ll.h[1] = __float2bfloat16(v1 - __bfloat162float(h1));
    *(uint32_t*)(Ch + off) = hh.u;
    *(uint32_t*)(Cl + off) = ll.u;
}

// ---------------------------------------------------------------------------
// Weight transpose + bf16 hi/lo split: W[K][N] fp32 -> Th/Tl[N][K] bf16 * scale
// ---------------------------------------------------------------------------
__global__ void __launch_bounds__(256) wtrans_kernel(
    const float* __restrict__ W, __nv_bfloat16* __restrict__ Th,
    __nv_bfloat16* __restrict__ Tl, float scale)
{
    __shared__ float t[32][33];
    int bx = blockIdx.x << 5;
    int by = blockIdx.y << 5;
    int x = threadIdx.x & 31, y = threadIdx.x >> 5;
    #pragma unroll
    for (int r = 0; r < 32; r += 8)
        t[y + r][x] = W[(size_t)(by + y + r) * DM + bx + x];
    __syncthreads();
    #pragma unroll
    for (int r = 0; r < 32; r += 8) {
        int nl = y + r;
        float v = t[x][nl] * scale;
        __nv_bfloat16 h = __float2bfloat16(v);
        __nv_bfloat16 l = __float2bfloat16(v - __bfloat162float(h));
        size_t o = (size_t)(bx + nl) * DM + by + x;
        Th[o] = h;
        Tl[o] = l;
    }
}

// ---------------------------------------------------------------------------
// Activation split: fp32 -> bf16 hi + lo
// ---------------------------------------------------------------------------
__global__ void __launch_bounds__(256) asplit_kernel(
    const float4* __restrict__ A, uint2* __restrict__ Ah, uint2* __restrict__ Al)
{
    int i = blockIdx.x * 256 + threadIdx.x;
    float4 v = A[i];
    float f[4] = {v.x, v.y, v.z, v.w};
    U4 ph, pl;
    #pragma unroll
    for (int j = 0; j < 4; j++) {
        __nv_bfloat16 h = __float2bfloat16(f[j]);
        ph.h[j] = h;
        pl.h[j] = __float2bfloat16(f[j] - __bfloat162float(h));
    }
    Ah[i] = ph.u;
    Al[i] = pl.u;
}

// ---------------------------------------------------------------------------
// Block-wide sum over 256 threads.
// ---------------------------------------------------------------------------
__device__ __forceinline__ float blk_sum256(float v, float* sbuf) {
    #pragma unroll
    for (int o = 16; o; o >>= 1) v += __shfl_xor_sync(0xffffffffu, v, o);
    int t = threadIdx.x;
    if ((t & 31) == 0) sbuf[t >> 5] = v;
    __syncthreads();
    float r = sbuf[0] + sbuf[1] + sbuf[2] + sbuf[3] +
              sbuf[4] + sbuf[5] + sbuf[6] + sbuf[7];
    __syncthreads();
    return r;
}

// ---------------------------------------------------------------------------
// LayerNorm over rows of 1024, output split to bf16 hi/lo.
// ---------------------------------------------------------------------------
__global__ void __launch_bounds__(256) ln_split_kernel(
    const float* __restrict__ x, const float* __restrict__ gamma,
    const float* __restrict__ beta, uint2* __restrict__ Yh, uint2* __restrict__ Yl)
{
    __shared__ float sbuf[8];
    int rowi = blockIdx.x;
    int t = threadIdx.x;
    const float4* xr = (const float4*)(x + (size_t)rowi * DM);
    float4 v = xr[t];
    float s = v.x + v.y + v.z + v.w;
    float tot = blk_sum256(s, sbuf);
    float mean = tot * (1.0f / DM);
    float dx = v.x - mean, dy = v.y - mean, dz = v.z - mean, dw = v.w - mean;
    float s2 = dx*dx + dy*dy + dz*dz + dw*dw;
    float tot2 = blk_sum256(s2, sbuf);
    float rstd = rsqrtf(tot2 * (1.0f / DM) + 1e-6f);
    float4 g  = ((const float4*)gamma)[t];
    float4 bb = ((const float4*)beta)[t];
    float o[4];
    o[0] = dx * rstd * g.x + bb.x;
    o[1] = dy * rstd * g.y + bb.y;
    o[2] = dz * rstd * g.z + bb.z;
    o[3] = dw * rstd * g.w + bb.w;
    U4 ph, pl;
    #pragma unroll
    for (int j = 0; j < 4; j++) {
        __nv_bfloat16 h = __float2bfloat16(o[j]);
        ph.h[j] = h;
        pl.h[j] = __float2bfloat16(o[j] - __bfloat162float(h));
    }
    Yh[rowi * 256 + t] = ph.u;
    Yl[rowi * 256 + t] = pl.u;
}

// ---------------------------------------------------------------------------
// HMMA GEMM v2: C = (Ah+Al)[8192][1024] @ (Bh+Bl)^T  (+R)
// KC=16 chunks, 4-stage cp.async ring, single sync per chunk, B via ldmat4.
// Stage: Ah|Al|Bh|Bl, each 128 rows x 24 elems (16 data + 8 pad; 48B stride
// is ldmatrix-conflict-free: banks r*12 mod 32 all distinct).
// ---------------------------------------------------------------------------
#define STG2      24
#define ARR2_B    (128 * STG2 * 2)       // 6144 B
#define STAGE2_B  (4 * ARR2_B)           // 24576 B
#define GEMM_SMEM (4 * STAGE2_B)         // 98304 B

__global__ void __launch_bounds__(256, 2) hmma_gemm(
    const __nv_bfloat16* __restrict__ Ah, const __nv_bfloat16* __restrict__ Al,
    const __nv_bfloat16* __restrict__ Bh, const __nv_bfloat16* __restrict__ Bl,
    const float* __restrict__ R, float* __restrict__ C,
    __nv_bfloat16* __restrict__ Ch, __nv_bfloat16* __restrict__ Cl)
{
    extern __shared__ char dynsm[];
    uint32_t sbase = smem_u32(dynsm);

    int tid = threadIdx.x, lane = tid & 31, wid = tid >> 5;
    int wm = (wid & 1) << 6;
    int wn = (wid >> 1) << 5;
    int bm = blockIdx.y << 7, bn = blockIdx.x << 7;

    float acc[4][4][4];
    #pragma unroll
    for (int mt = 0; mt < 4; mt++)
        #pragma unroll
        for (int nt = 0; nt < 4; nt++)
            #pragma unroll
            for (int e = 0; e < 4; e++) acc[mt][nt][e] = 0.0f;

    int l_row = tid >> 1;
    int l_seg = tid & 1;

    #define LOAD_STAGE(s, kc) do {                                            \
        uint32_t d_ = sbase + (s) * STAGE2_B + l_row * 48 + l_seg * 16;       \
        const __nv_bfloat16* a_ = Ah + (size_t)(bm + l_row) * DM              \
                                  + ((kc) << 4) + l_seg * 8;                  \
        const __nv_bfloat16* b_ = Bh + (size_t)(bn + l_row) * DM              \
                                  + ((kc) << 4) + l_seg * 8;                  \
        cpasync16(d_,              a_);                                       \
        cpasync16(d_ + ARR2_B,     a_ + (Al - Ah));                           \
        cpasync16(d_ + 2 * ARR2_B, b_);                                       \
        cpasync16(d_ + 3 * ARR2_B, b_ + (Bl - Bh));                           \
        CP_COMMIT();                                                          \
    } while (0)

    LOAD_STAGE(0, 0);
    LOAD_STAGE(1, 1);
    LOAD_STAGE(2, 2);

    const int NK = DM / 16;   // 64 chunks
    for (int kc = 0; kc < NK; kc++) {
        if (kc < NK - 3) CP_WAIT2();
        else             CP_WAIT0();
        __syncthreads();
        if (kc + 3 < NK) LOAD_STAGE((kc + 3) & 3, kc + 3);

        uint32_t sb = sbase + (kc & 3) * STAGE2_B;
        uint32_t ah[4][4], al[4][4];
        uint32_t a_addr = sb + (wm + (lane & 15)) * 48 + ((lane >> 4) << 4);
        #pragma unroll
        for (int mt = 0; mt < 4; mt++) {
            ldmat4(ah[mt], a_addr + mt * (16 * 48));
            ldmat4(al[mt], a_addr + mt * (16 * 48) + ARR2_B);
        }
        #pragma unroll
        for (int p = 0; p < 2; p++) {
            uint32_t bh4[4], bl4[4];
            uint32_t b_addr = sb + 2 * ARR2_B +
                (wn + (p << 4) + (lane & 7) + ((lane >> 4) << 3)) * 48 +
                (((lane >> 3) & 1) << 4);
            ldmat4(bh4, b_addr);
            ldmat4(bl4, b_addr + ARR2_B);
            #pragma unroll
            for (int mt = 0; mt < 4; mt++) {
                mma_bf16(acc[mt][2 * p],     ah[mt], bh4);
                mma_bf16(acc[mt][2 * p],     ah[mt], bl4);
                mma_bf16(acc[mt][2 * p],     al[mt], bh4);
                mma_bf16(acc[mt][2 * p + 1], ah[mt], bh4 + 2);
                mma_bf16(acc[mt][2 * p + 1], ah[mt], bl4 + 2);
                mma_bf16(acc[mt][2 * p + 1], al[mt], bh4 + 2);
            }
        }
    }

    int rq = lane >> 2, cq = (lane & 3) << 1;
    if (C) {
        #pragma unroll
        for (int mt = 0; mt < 4; mt++) {
            int r0 = bm + wm + (mt << 4) + rq;
            #pragma unroll
            for (int nt = 0; nt < 4; nt++) {
                int c = bn + wn + (nt << 3) + cq;
                float2 v0 = make_float2(acc[mt][nt][0], acc[mt][nt][1]);
                float2 v1 = make_float2(acc[mt][nt][2], acc[mt][nt][3]);
                if (R) {
                    float2 r0v = *(const float2*)(R + (size_t)r0 * DM + c);
                    float2 r1v = *(const float2*)(R + (size_t)(r0 + 8) * DM + c);
                    v0.x += r0v.x; v0.y += r0v.y;
                    v1.x += r1v.x; v1.y += r1v.y;
                }
                *(float2*)(C + (size_t)r0 * DM + c) = v0;
                *(float2*)(C + (size_t)(r0 + 8) * DM + c) = v1;
            }
        }
    } else {
        #pragma unroll
        for (int mt = 0; mt < 4; mt++) {
            int r0 = bm + wm + (mt << 4) + rq;
            #pragma unroll
            for (int nt = 0; nt < 4; nt++) {
                int c = bn + wn + (nt << 3) + cq;
                store2_split(Ch, Cl, (size_t)r0 * DM + c,
                             acc[mt][nt][0], acc[mt][nt][1]);
                store2_split(Ch, Cl, (size_t)(r0 + 8) * DM + c,
                             acc[mt][nt][2], acc[mt][nt][3]);
            }
        }
    }
    #undef LOAD_STAGE
}

// ---------------------------------------------------------------------------
// V transpose: Vs hi/lo [8192][1024] -> Vt hi/lo [bh][64 d][2048 s]
// ---------------------------------------------------------------------------
__global__ void __launch_bounds__(256) vtrans_kernel(
    const __nv_bfloat16* __restrict__ Vh, const __nv_bfloat16* __restrict__ Vl,
    __nv_bfloat16* __restrict__ Th, __nv_bfloat16* __restrict__ Tl)
{
    __shared__ __nv_bfloat16 th[32][33], tl[32][33];
    int rt = blockIdx.x << 5;
    int ct = blockIdx.y << 5;
    int x = threadIdx.x & 31, y = threadIdx.x >> 5;
    #pragma unroll
    for (int r = 0; r < 32; r += 8) {
        th[y + r][x] = Vh[(size_t)(rt + y + r) * DM + ct + x];
        tl[y + r][x] = Vl[(size_t)(rt + y + r) * DM + ct + x];
    }
    __syncthreads();
    int b = rt >> 11;
    int s0 = rt & 2047;
    #pragma unroll
    for (int r = 0; r < 32; r += 8) {
        int col = ct + y + r;
        int h = col >> 6, d = col & 63;
        size_t o = ((size_t)(b * H_ + h) * DK + d) * S_ + s0 + x;
        Th[o] = th[x][y + r];
        Tl[o] = tl[x][y + r];
    }
}

// ---------------------------------------------------------------------------
// scores2: per block 128 q-rows x full 2048 k.  Warp owns 16 rows.
// Q fragments hoisted to registers once; each 128-col k-tile processed in
// two 64-col halves.  Writes E = exp(s - m_t), m_t per (row, 64-col tile),
// final (M, sigma) per row.
// ---------------------------------------------------------------------------
__global__ void __launch_bounds__(256, 2) scores2_kernel(
    const __nv_bfloat16* __restrict__ Qsh, const __nv_bfloat16* __restrict__ Qsl,
    const __nv_bfloat16* __restrict__ Ksh, const __nv_bfloat16* __restrict__ Ksl,
    const int* __restrict__ mask, float* __restrict__ attn,
    float* __restrict__ tm, float* __restrict__ rowM, float* __restrict__ rowS)
{
    extern __shared__ char dsm[];
    uint32_t sb = smem_u32(dsm);
    const uint32_t sQh = sb;
    const uint32_t sQl = sb + 18432;
    const uint32_t sKh = sb + 36864;
    const uint32_t sKl = sb + 73728;
    __shared__ int msk[2][128];

    int tid = threadIdx.x, lane = tid & 31, wid = tid >> 5;
    int bh = blockIdx.y, b = bh >> 4, h = bh & 15;
    int q0 = blockIdx.x << 7;
    int ql = lane >> 2, cq = (lane & 3) << 1;

    #pragma unroll
    for (int i = 0; i < 4; i++) {
        int sidx = tid + (i << 8);
        int row = sidx >> 3, off = (sidx & 7) << 3;
        uint32_t d = (uint32_t)((row * 72 + off) << 1);
        size_t go = (size_t)(b * S_ + q0 + row) * DM + h * DK + off;
        cpasync16(sQh + d, Qsh + go);
        cpasync16(sQl + d, Qsl + go);
    }

    #define LOADK(st, kt) do {                                                \
        int kb_ = (kt) << 7;                                                  \
        if (tid < 128) msk[st][tid] = mask[b * S_ + kb_ + tid];               \
        _Pragma("unroll")                                                     \
        for (int i = 0; i < 4; i++) {                                         \
            int sidx = tid + (i << 8);                                        \
            int row = sidx >> 3, off = (sidx & 7) << 3;                       \
            uint32_t d = (uint32_t)(((st) * 18432) + ((row * 72 + off) << 1));\
            size_t go = (size_t)(b * S_ + kb_ + row) * DM + h * DK + off;     \
            cpasync16(sKh + d, Ksh + go);                                     \
            cpasync16(sKl + d, Ksl + go);                                     \
        }                                                                     \
    } while (0)

    LOADK(0, 0);
    CP_COMMIT();
    LOADK(1, 1);
    CP_COMMIT();
    CP_WAIT1();            // Q + K0 ready
    __syncthreads();

    // Hoist Q fragments (4 k-steps x hi/lo)
    uint32_t qh4[4][4], ql4[4][4];
    #pragma unroll
    for (int ks = 0; ks < 4; ks++) {
        uint32_t aaddr = sQh +
            ((((wid << 4) + (lane & 15)) * 72 + (ks << 4) +
              ((lane >> 4) << 3)) << 1);
        ldmat4(qh4[ks], aaddr);
        ldmat4(ql4[ks], aaddr + 18432);
    }

    float m0 = -3.0e38f, m1 = -3.0e38f, sg0 = 0.0f, sg1 = 0.0f;
    int wrow = (wid << 4) + ql;
    size_t R0 = (size_t)bh * S_ + q0 + wrow;

    for (int kt = 0; kt < 16; kt++) {
        int st = kt & 1;
        uint32_t kbase = sKh + st * 18432;
        int kb = kt << 7;

        #pragma unroll
        for (int hf = 0; hf < 2; hf++) {
            float acc[8][4];
            #pragma unroll
            for (int nt = 0; nt < 8; nt++)
                #pragma unroll
                for (int e = 0; e < 4; e++) acc[nt][e] = 0.0f;

            #pragma unroll
            for (int ks = 0; ks < 4; ks++) {
                #pragma unroll
                for (int p = 0; p < 4; p++) {
                    int pp = (hf << 2) + p;
                    uint32_t bh4[4], bl4[4];
                    uint32_t baddr = kbase +
                        ((((pp << 4) + (lane & 7) + ((lane >> 4) << 3)) * 72 +
                          (ks << 4) + (((lane >> 3) & 1) << 3)) << 1);
                    ldmat4(bh4, baddr);
                    ldmat4(bl4, baddr + 36864);
                    mma_bf16(acc[2 * p],     qh4[ks], bh4);
                    mma_bf16(acc[2 * p],     qh4[ks], bl4);
                    mma_bf16(acc[2 * p],     ql4[ks], bh4);
                    mma_bf16(acc[2 * p + 1], qh4[ks], bh4 + 2);
                    mma_bf16(acc[2 * p + 1], qh4[ks], bl4 + 2);
                    mma_bf16(acc[2 * p + 1], ql4[ks], bh4 + 2);
                }
            }

            float mx0 = -3.0e38f, mx1 = -3.0e38f;
            #pragma unroll
            for (int nt = 0; nt < 8; nt++) {
                int c0 = (hf << 6) + (nt << 3) + cq;
                bool k0m = msk[st][c0] != 0;
                bool k1m = msk[st][c0 + 1] != 0;
                acc[nt][0] = k0m ? acc[nt][0] : NEG_INF_F;
                acc[nt][1] = k1m ? acc[nt][1] : NEG_INF_F;
                acc[nt][2] = k0m ? acc[nt][2] : NEG_INF_F;
                acc[nt][3] = k1m ? acc[nt][3] : NEG_INF_F;
                mx0 = fmaxf(mx0, fmaxf(acc[nt][0], acc[nt][1]));
                mx1 = fmaxf(mx1, fmaxf(acc[nt][2], acc[nt][3]));
            }
            mx0 = fmaxf(mx0, __shfl_xor_sync(0xffffffffu, mx0, 1));
            mx0 = fmaxf(mx0, __shfl_xor_sync(0xffffffffu, mx0, 2));
            mx1 = fmaxf(mx1, __shfl_xor_sync(0xffffffffu, mx1, 1));
            mx1 = fmaxf(mx1, __shfl_xor_sync(0xffffffffu, mx1, 2));
            float mp0 = m0; m0 = fmaxf(m0, mx0); sg0 *= __expf(mp0 - m0);
            float mp1 = m1; m1 = fmaxf(m1, mx1); sg1 *= __expf(mp1 - m1);

            float* o0 = attn + R0 * S_ + kb;
            float* o1 = attn + (R0 + 8) * S_ + kb;
            #pragma unroll
            for (int nt = 0; nt < 8; nt++) {
                int c0 = (hf << 6) + (nt << 3) + cq;
                float e0 = __expf(acc[nt][0] - m0), e1 = __expf(acc[nt][1] - m0);
                float e2 = __expf(acc[nt][2] - m1), e3 = __expf(acc[nt][3] - m1);
                sg0 += e0 + e1;
                sg1 += e2 + e3;
                *(float2*)(o0 + c0) = make_float2(e0, e1);
                *(float2*)(o1 + c0) = make_float2(e2, e3);
            }
            if ((lane & 3) == 0) {
                int t2 = (kt << 1) + hf;
                tm[R0 * NTILE + t2]       = m0;
                tm[(R0 + 8) * NTILE + t2] = m1;
            }
        }

        __syncthreads();                 // all warps done reading stage st
        if (kt + 2 < 16) {
            LOADK(st, kt + 2);
            CP_COMMIT();
            CP_WAIT1();                  // stage st^1 (tile kt+1) ready
        } else {
            CP_WAIT0();
        }
        __syncthreads();
    }

    sg0 += __shfl_xor_sync(0xffffffffu, sg0, 1);
    sg0 += __shfl_xor_sync(0xffffffffu, sg0, 2);
    sg1 += __shfl_xor_sync(0xffffffffu, sg1, 1);
    sg1 += __shfl_xor_sync(0xffffffffu, sg1, 2);
    if ((lane & 3) == 0) {
        rowM[R0] = m0;      rowS[R0] = sg0;
        rowM[R0 + 8] = m1;  rowS[R0 + 8] = sg1;
    }
    #undef LOADK
}

// ---------------------------------------------------------------------------
// finalize: scale[row][tile] = exp(m_t - M) / sigma   (NTILE per row)
// ---------------------------------------------------------------------------
__global__ void __launch_bounds__(256) fin_kernel(
    const float* __restrict__ tm, const float* __restrict__ rM,
    const float* __restrict__ rS, float* __restrict__ tsc)
{
    int i = blockIdx.x * 256 + threadIdx.x;
    int R = i >> 5;           // NTILE = 32
    tsc[i] = __expf(tm[i] - rM[R]) / rS[R];
}

// ---------------------------------------------------------------------------
// normPV: p = E * scale (coalesced in-place normalize), ctx = P @ V (HMMA),
// ctx written as bf16 hi/lo.  Warp sweeps 16 rows; lanes cover 128 cols.
// ---------------------------------------------------------------------------
__global__ void __launch_bounds__(256, 2) normpv_kernel(
    float* __restrict__ attn, const float* __restrict__ tsc,
    const __nv_bfloat16* __restrict__ Vth, const __nv_bfloat16* __restrict__ Vtl,
    __nv_bfloat16* __restrict__ Ch, __nv_bfloat16* __restrict__ Cl)
{
    extern __shared__ char dsm[];
    uint32_t sb = smem_u32(dsm);
    const uint32_t sPh = sb;
    const uint32_t sPl = sb + 34816;
    const uint32_t sVh = sb + 69632;
    const uint32_t sVl = sb + 87040;

    int tid = threadIdx.x, lane = tid & 31, wid = tid >> 5;
    int bh = blockIdx.y, b = bh >> 4, h = bh & 15;
    int q0 = blockIdx.x << 7;
    int wm = (wid & 3) << 5, wn = (wid >> 2) << 5;
    int rq = lane >> 2, cq = (lane & 3) << 1;

    float acc[2][4][4];
    #pragma unroll
    for (int mt = 0; mt < 2; mt++)
        #pragma unroll
        for (int nt = 0; nt < 4; nt++)
            #pragma unroll
            for (int e = 0; e < 4; e++) acc[mt][nt][e] = 0.0f;

    size_t Rbase = (size_t)bh * S_ + q0 + (wid << 4);

    for (int kt = 0; kt < 16; kt++) {
        int kb = kt << 7;
        #pragma unroll
        for (int i = 0; i < 4; i++) {
            int sidx = tid + (i << 8);
            int d = sidx >> 4, off = (sidx & 15) << 3;
            uint32_t dst = (uint32_t)((d * 136 + off) << 1);
            size_t go = ((size_t)bh * DK + d) * S_ + kb + off;
            cpasync16(sVh + dst, Vth + go);
            cpasync16(sVl + dst, Vtl + go);
        }
        CP_COMMIT();

        #pragma unroll 4
        for (int r = 0; r < 16; r++) {
            int row = (wid << 4) + r;
            size_t Rr = Rbase + r;
            float sc = tsc[Rr * NTILE + (kt << 1) + (lane >> 4)];
            float* erow = attn + Rr * S_ + kb + (lane << 2);
            float4 vv = *(const float4*)erow;
            float p0 = vv.x * sc, p1 = vv.y * sc, p2 = vv.z * sc, p3 = vv.w * sc;
            *(float4*)erow = make_float4(p0, p1, p2, p3);
            U4 hh, ll;
            __nv_bfloat16 b0 = __float2bfloat16(p0);
            __nv_bfloat16 b1 = __float2bfloat16(p1);
            __nv_bfloat16 b2 = __float2bfloat16(p2);
            __nv_bfloat16 b3 = __float2bfloat16(p3);
            hh.h[0] = b0; hh.h[1] = b1; hh.h[2] = b2; hh.h[3] = b3;
            ll.h[0] = __float2bfloat16(p0 - __bfloat162float(b0));
            ll.h[1] = __float2bfloat16(p1 - __bfloat162float(b1));
            ll.h[2] = __float2bfloat16(p2 - __bfloat162float(b2));
            ll.h[3] = __float2bfloat16(p3 - __bfloat162float(b3));
            uint32_t doff = (uint32_t)((row * 136 + (lane << 2)) << 1);
            sts64(sPh + doff, hh.u);
            sts64(sPl + doff, ll.u);
        }
        CP_WAIT0();
        __syncthreads();

        #pragma unroll
        for (int ks = 0; ks < 8; ks++) {
            uint32_t ah4[2][4], al4[2][4];
            #pragma unroll
            for (int mt = 0; mt < 2; mt++) {
                uint32_t aaddr = sPh +
                    (((wm + (mt << 4) + (lane & 15)) * 136 +
                      (ks << 4) + ((lane >> 4) << 3)) << 1);
                ldmat4(ah4[mt], aaddr);
                ldmat4(al4[mt], aaddr + 34816);
            }
            #pragma unroll
            for (int p = 0; p < 2; p++) {
                uint32_t bh4[4], bl4[4];
                uint32_t baddr = sVh +
                    (((wn + (p << 4) + (lane & 7) + ((lane >> 4) << 3)) * 136 +
                      (ks << 4) + (((lane >> 3) & 1) << 3)) << 1);
                ldmat4(bh4, baddr);
                ldmat4(bl4, baddr + 17408);
                #pragma unroll
                for (int mt = 0; mt < 2; mt++) {
                    mma_bf16(acc[mt][2 * p],     ah4[mt], bh4);
                    mma_bf16(acc[mt][2 * p],     ah4[mt], bl4);
                    mma_bf16(acc[mt][2 * p],     al4[mt], bh4);
                    mma_bf16(acc[mt][2 * p + 1], ah4[mt], bh4 + 2);
                    mma_bf16(acc[mt][2 * p + 1], ah4[mt], bl4 + 2);
                    mma_bf16(acc[mt][2 * p + 1], al4[mt], bh4 + 2);
                }
            }
        }
        __syncthreads();
    }

    #pragma unroll
    for (int mt = 0; mt < 2; mt++) {
        int row = b * S_ + q0 + wm + (mt << 4) + rq;
        #pragma unroll
        for (int nt = 0; nt < 4; nt++) {
            int col = h * DK + wn + (nt << 3) + cq;
            store2_split(Ch, Cl, (size_t)row * DM + col,
                         acc[mt][nt][0], acc[mt][nt][1]);
            store2_split(Ch, Cl, (size_t)(row + 8) * DM + col,
                         acc[mt][nt][2], acc[mt][nt][3]);
        }
    }
}

// ---------------------------------------------------------------------------
extern "C" void kernel_launch(void* const* d_in, const int* in_sizes, int n_in,
                              void* d_out, int out_size)
{
    const float* q    = (const float*)d_in[0];
    const float* k    = (const float*)d_in[1];
    const float* v    = (const float*)d_in[2];
    const int*   mask = (const int*)  d_in[3];
    const float* Wq   = (const float*)d_in[4];
    const float* Wk   = (const float*)d_in[5];
    const float* Wv   = (const float*)d_in[6];
    const float* Wo   = (const float*)d_in[7];
    const float* lg   = (const float*)d_in[8];
    const float* lb   = (const float*)d_in[9];

    float* out  = (float*)d_out;
    float* attn = out + ATTN_OFF;

    __nv_bfloat16 *WTh, *WTl, *Ah, *Al, *Qsh, *Qsl, *Ksh, *Ksl, *Vsh, *Vsl,
                  *Vth, *Vtl, *Ch, *Cl;
    float *tm, *tsc, *rM, *rS;
    cudaGetSymbolAddress((void**)&WTh, g_WTh);
    cudaGetSymbolAddress((void**)&WTl, g_WTl);
    cudaGetSymbolAddress((void**)&Ah,  g_Ah);
    cudaGetSymbolAddress((void**)&Al,  g_Al);
    cudaGetSymbolAddress((void**)&Qsh, g_Qsh);
    cudaGetSymbolAddress((void**)&Qsl, g_Qsl);
    cudaGetSymbolAddress((void**)&Ksh, g_Ksh);
    cudaGetSymbolAddress((void**)&Ksl, g_Ksl);
    cudaGetSymbolAddress((void**)&Vsh, g_Vsh);
    cudaGetSymbolAddress((void**)&Vsl, g_Vsl);
    cudaGetSymbolAddress((void**)&Vth, g_Vth);
    cudaGetSymbolAddress((void**)&Vtl, g_Vtl);
    cudaGetSymbolAddress((void**)&Ch,  g_Ch);
    cudaGetSymbolAddress((void**)&Cl,  g_Cl);
    cudaGetSymbolAddress((void**)&tm,  g_tm);
    cudaGetSymbolAddress((void**)&tsc, g_tsc);
    cudaGetSymbolAddress((void**)&rM,  g_rowM);
    cudaGetSymbolAddress((void**)&rS,  g_rowS);

    cudaFuncSetAttribute(hmma_gemm,
                         cudaFuncAttributeMaxDynamicSharedMemorySize, GEMM_SMEM);
    cudaFuncSetAttribute(scores2_kernel,
                         cudaFuncAttributeMaxDynamicSharedMemorySize, 110592);
    cudaFuncSetAttribute(normpv_kernel,
                         cudaFuncAttributeMaxDynamicSharedMemorySize, 104448);

    const int WSZ = DM * DM;
    dim3 gt(32, 32);

    // 0. Weight transpose + split (Wq folded with 1/sqrt(DK) = 0.125)
    wtrans_kernel<<<gt, 256>>>(Wq, WTh + 0 * WSZ, WTl + 0 * WSZ, 0.125f);
    wtrans_kernel<<<gt, 256>>>(Wk, WTh + 1 * WSZ, WTl + 1 * WSZ, 1.0f);
    wtrans_kernel<<<gt, 256>>>(Wv, WTh + 2 * WSZ, WTl + 2 * WSZ, 1.0f);
    wtrans_kernel<<<gt, 256>>>(Wo, WTh + 3 * WSZ, WTl + 3 * WSZ, 1.0f);

    // 1. LayerNorm(q) -> split
    ln_split_kernel<<<BS_, 256>>>(q, lg, lb, (uint2*)Ah, (uint2*)Al);

    const int ASPLIT_G = BS_ * DM / 4 / 256;
    dim3 gg(DM / 128, BS_ / 128);

    // 2-4. Projections (outputs split bf16)
    hmma_gemm<<<gg, 256, GEMM_SMEM>>>(Ah, Al, WTh + 0 * WSZ, WTl + 0 * WSZ,
                                      nullptr, nullptr, Qsh, Qsl);
    asplit_kernel<<<ASPLIT_G, 256>>>((const float4*)k, (uint2*)Ah, (uint2*)Al);
    hmma_gemm<<<gg, 256, GEMM_SMEM>>>(Ah, Al, WTh + 1 * WSZ, WTl + 1 * WSZ,
                                      nullptr, nullptr, Ksh, Ksl);
    asplit_kernel<<<ASPLIT_G, 256>>>((const float4*)v, (uint2*)Ah, (uint2*)Al);
    hmma_gemm<<<gg, 256, GEMM_SMEM>>>(Ah, Al, WTh + 2 * WSZ, WTl + 2 * WSZ,
                                      nullptr, nullptr, Vsh, Vsl);

    // 5. V transpose to [bh][d][s]
    vtrans_kernel<<<dim3(BS_ / 32, DM / 32), 256>>>(Vsh, Vsl, Vth, Vtl);

    // 6. Scores: E = exp(s - m_t) with per-64-col-tile m_t
    scores2_kernel<<<dim3(S_ / 128, B_ * H_), 256, 110592>>>(
        Qsh, Qsl, Ksh, Ksl, mask, attn, tm, rM, rS);

    // 7. Per-(row, 64-col tile) scales
    fin_kernel<<<(NROW * NTILE) / 256, 256>>>(tm, rM, rS, tsc);

    // 8. Normalize probs in place + PV (ctx split bf16)
    normpv_kernel<<<dim3(S_ / 128, B_ * H_), 256, 104448>>>(
        attn, tsc, Vth, Vtl, Ch, Cl);

    // 9. Output projection + residual
    hmma_gemm<<<gg, 256, GEMM_SMEM>>>(Ch, Cl, WTh + 3 * WSZ, WTl + 3 * WSZ,
                                      q, out, nullptr, nullptr);
}

// round 16
// speedup vs baseline: 2.2550x; 1.1135x over previous
#include <cuda_runtime.h>
#include <cuda_bf16.h>
#include <math.h>
#include <stdint.h>

// ---------------------------------------------------------------------------
// MultiHeadAttention: B=4, S=2048, D_MODEL=1024, HEADS=16, D_K=D_V=64
// Output: concat( out[B,S,1024], attn[B,H,S,S] ) fp32
// Q/K path: HMMA bf16 hi/lo split-3 (full accuracy -> attn probs exact-ish).
// V/ctx/Wo path: reduced-term HMMA (out-norm error budget has ~80x slack).
// ---------------------------------------------------------------------------

#define B_   4
#define S_   2048
#define DM   1024
#define H_   16
#define DK   64
#define BS_  (B_ * S_)                 // 8192
#define NROW (B_ * H_ * S_)            // 131072
#define NTILE 32                        // 64-col score tiles per row
#define ATTN_OFF ((size_t)BS_ * DM)
#define NEG_INF_F (-1000000000.0f)

// Scratch (static device globals; no runtime allocation)
__device__ __align__(16) __nv_bfloat16 g_WTh[4][DM * DM];
__device__ __align__(16) __nv_bfloat16 g_WTl[4][DM * DM];
__device__ __align__(16) __nv_bfloat16 g_Ah [BS_ * DM];   // ln(q) split hi
__device__ __align__(16) __nv_bfloat16 g_Al [BS_ * DM];   // ln(q) split lo
__device__ __align__(16) __nv_bfloat16 g_Qsh[BS_ * DM];
__device__ __align__(16) __nv_bfloat16 g_Qsl[BS_ * DM];
__device__ __align__(16) __nv_bfloat16 g_Ksh[BS_ * DM];
__device__ __align__(16) __nv_bfloat16 g_Ksl[BS_ * DM];
__device__ __align__(16) __nv_bfloat16 g_Vsh[BS_ * DM];
__device__ __align__(16) __nv_bfloat16 g_Vsl[BS_ * DM];
__device__ __align__(16) __nv_bfloat16 g_Vth[BS_ * DM];   // also V-split input
__device__ __align__(16) __nv_bfloat16 g_Vtl[BS_ * DM];
__device__ __align__(16) __nv_bfloat16 g_Ch [BS_ * DM];   // K-split in, then ctx
__device__ __align__(16) __nv_bfloat16 g_Cl [BS_ * DM];   // K-split lo
__device__ float g_tm  [(size_t)NROW * NTILE];
__device__ float g_tsc [(size_t)NROW * NTILE];
__device__ float g_rowM[NROW];
__device__ float g_rowS[NROW];

// ============================ PTX helpers ==================================
__device__ __forceinline__ uint32_t smem_u32(const void* p) {
    uint32_t a;
    asm("{ .reg .u64 t; cvta.to.shared.u64 t, %1; cvt.u32.u64 %0, t; }"
        : "=r"(a) : "l"(p));
    return a;
}
__device__ __forceinline__ void ldmat4(uint32_t* r, uint32_t addr) {
    asm volatile("ldmatrix.sync.aligned.m8n8.x4.shared.b16 {%0,%1,%2,%3}, [%4];"
                 : "=r"(r[0]), "=r"(r[1]), "=r"(r[2]), "=r"(r[3]) : "r"(addr));
}
__device__ __forceinline__ void mma_bf16(float* d, const uint32_t* a,
                                         const uint32_t* b) {
    asm volatile(
        "mma.sync.aligned.m16n8k16.row.col.f32.bf16.bf16.f32 "
        "{%0,%1,%2,%3}, {%4,%5,%6,%7}, {%8,%9}, {%0,%1,%2,%3};"
        : "+f"(d[0]), "+f"(d[1]), "+f"(d[2]), "+f"(d[3])
        : "r"(a[0]), "r"(a[1]), "r"(a[2]), "r"(a[3]), "r"(b[0]), "r"(b[1]));
}
__device__ __forceinline__ void cpasync16(uint32_t dst, const void* src) {
    asm volatile("cp.async.cg.shared.global [%0], [%1], 16;"
                 :: "r"(dst), "l"(src));
}
#define CP_COMMIT() asm volatile("cp.async.commit_group;" ::: "memory")
#define CP_WAIT2()  asm volatile("cp.async.wait_group 2;"  ::: "memory")
#define CP_WAIT1()  asm volatile("cp.async.wait_group 1;"  ::: "memory")
#define CP_WAIT0()  asm volatile("cp.async.wait_group 0;"  ::: "memory")
__device__ __forceinline__ void sts64(uint32_t addr, uint2 v) {
    asm volatile("st.shared.v2.b32 [%0], {%1,%2};"
                 :: "r"(addr), "r"(v.x), "r"(v.y) : "memory");
}

union U4  { __nv_bfloat16 h[4]; uint2 u; };
union U2  { __nv_bfloat16 h[2]; uint32_t u; };

__device__ __forceinline__ void store2_split(__nv_bfloat16* Ch, __nv_bfloat16* Cl,
                                             size_t off, float v0, float v1) {
    U2 hh, ll;
    __nv_bfloat16 h0 = __float2bfloat16(v0), h1 = __float2bfloat16(v1);
    hh.h[0] = h0; hh.h[1] = h1;
    ll.h[0] = __float2bfloat16(v0 - __bfloat162float(h0));
    ll.h[1] = __float2bfloat16(v1 - __bfloat162float(h1));
    *(uint32_t*)(Ch + off) = hh.u;
    *(uint32_t*)(Cl + off) = ll.u;
}

// ---------------------------------------------------------------------------
// Batched weight transpose + split: 4 matrices, grid.z selects.
// ---------------------------------------------------------------------------
__global__ void __launch_bounds__(256) wtrans4_kernel(
    const float* __restrict__ W0, const float* __restrict__ W1,
    const float* __restrict__ W2, const float* __restrict__ W3,
    __nv_bfloat16* __restrict__ ThB, __nv_bfloat16* __restrict__ TlB)
{
    __shared__ float t[32][33];
    int z = blockIdx.z;
    const float* W = (z == 0) ? W0 : (z == 1) ? W1 : (z == 2) ? W2 : W3;
    float scale = (z == 0) ? 0.125f : 1.0f;
    __nv_bfloat16* Th = ThB + (size_t)z * DM * DM;
    __nv_bfloat16* Tl = TlB + (size_t)z * DM * DM;
    int bx = blockIdx.x << 5;
    int by = blockIdx.y << 5;
    int x = threadIdx.x & 31, y = threadIdx.x >> 5;
    #pragma unroll
    for (int r = 0; r < 32; r += 8)
        t[y + r][x] = W[(size_t)(by + y + r) * DM + bx + x];
    __syncthreads();
    #pragma unroll
    for (int r = 0; r < 32; r += 8) {
        int nl = y + r;
        float v = t[x][nl] * scale;
        __nv_bfloat16 h = __float2bfloat16(v);
        __nv_bfloat16 l = __float2bfloat16(v - __bfloat162float(h));
        size_t o = (size_t)(bx + nl) * DM + by + x;
        Th[o] = h;
        Tl[o] = l;
    }
}

// ---------------------------------------------------------------------------
// Batched activation split: grid.y selects (k -> Ch/Cl, v -> Vth/Vtl)
// ---------------------------------------------------------------------------
__global__ void __launch_bounds__(256) asplit2_kernel(
    const float4* __restrict__ A0, uint2* __restrict__ H0, uint2* __restrict__ L0,
    const float4* __restrict__ A1, uint2* __restrict__ H1, uint2* __restrict__ L1)
{
    int i = blockIdx.x * 256 + threadIdx.x;
    const float4* A = blockIdx.y ? A1 : A0;
    uint2* Hh = blockIdx.y ? H1 : H0;
    uint2* Ll = blockIdx.y ? L1 : L0;
    float4 v = A[i];
    float f[4] = {v.x, v.y, v.z, v.w};
    U4 ph, pl;
    #pragma unroll
    for (int j = 0; j < 4; j++) {
        __nv_bfloat16 h = __float2bfloat16(f[j]);
        ph.h[j] = h;
        pl.h[j] = __float2bfloat16(f[j] - __bfloat162float(h));
    }
    Hh[i] = ph.u;
    Ll[i] = pl.u;
}

// ---------------------------------------------------------------------------
// Block-wide sum over 256 threads.
// ---------------------------------------------------------------------------
__device__ __forceinline__ float blk_sum256(float v, float* sbuf) {
    #pragma unroll
    for (int o = 16; o; o >>= 1) v += __shfl_xor_sync(0xffffffffu, v, o);
    int t = threadIdx.x;
    if ((t & 31) == 0) sbuf[t >> 5] = v;
    __syncthreads();
    float r = sbuf[0] + sbuf[1] + sbuf[2] + sbuf[3] +
              sbuf[4] + sbuf[5] + sbuf[6] + sbuf[7];
    __syncthreads();
    return r;
}

// ---------------------------------------------------------------------------
// LayerNorm over rows of 1024, output split to bf16 hi/lo.
// ---------------------------------------------------------------------------
__global__ void __launch_bounds__(256) ln_split_kernel(
    const float* __restrict__ x, const float* __restrict__ gamma,
    const float* __restrict__ beta, uint2* __restrict__ Yh, uint2* __restrict__ Yl)
{
    __shared__ float sbuf[8];
    int rowi = blockIdx.x;
    int t = threadIdx.x;
    const float4* xr = (const float4*)(x + (size_t)rowi * DM);
    float4 v = xr[t];
    float s = v.x + v.y + v.z + v.w;
    float tot = blk_sum256(s, sbuf);
    float mean = tot * (1.0f / DM);
    float dx = v.x - mean, dy = v.y - mean, dz = v.z - mean, dw = v.w - mean;
    float s2 = dx*dx + dy*dy + dz*dz + dw*dw;
    float tot2 = blk_sum256(s2, sbuf);
    float rstd = rsqrtf(tot2 * (1.0f / DM) + 1e-6f);
    float4 g  = ((const float4*)gamma)[t];
    float4 bb = ((const float4*)beta)[t];
    float o[4];
    o[0] = dx * rstd * g.x + bb.x;
    o[1] = dy * rstd * g.y + bb.y;
    o[2] = dz * rstd * g.z + bb.z;
    o[3] = dw * rstd * g.w + bb.w;
    U4 ph, pl;
    #pragma unroll
    for (int j = 0; j < 4; j++) {
        __nv_bfloat16 h = __float2bfloat16(o[j]);
        ph.h[j] = h;
        pl.h[j] = __float2bfloat16(o[j] - __bfloat162float(h));
    }
    Yh[rowi * 256 + t] = ph.u;
    Yl[rowi * 256 + t] = pl.u;
}

// ---------------------------------------------------------------------------
// GEMM body: C = (Ah[+Al]) @ (Bh+Bl)^T (+R).  Al==null -> 2-term MMA.
// KC=16 chunks, 4-stage cp.async ring, single sync per chunk.
// ---------------------------------------------------------------------------
#define STG2      24
#define ARR2_B    (128 * STG2 * 2)       // 6144 B
#define STAGE2_B  (4 * ARR2_B)           // 24576 B
#define GEMM_SMEM (4 * STAGE2_B)         // 98304 B

__device__ __forceinline__ void gemm_body(
    const __nv_bfloat16* __restrict__ Ah, const __nv_bfloat16* __restrict__ Al,
    const __nv_bfloat16* __restrict__ Bh, const __nv_bfloat16* __restrict__ Bl,
    const float* __restrict__ R, float* __restrict__ C,
    __nv_bfloat16* __restrict__ Ch, __nv_bfloat16* __restrict__ Cl,
    char* dynsm)
{
    uint32_t sbase = smem_u32(dynsm);
    const bool has_al = (Al != nullptr);

    int tid = threadIdx.x, lane = tid & 31, wid = tid >> 5;
    int wm = (wid & 1) << 6;
    int wn = (wid >> 1) << 5;
    int bm = blockIdx.y << 7, bn = blockIdx.x << 7;

    float acc[4][4][4];
    #pragma unroll
    for (int mt = 0; mt < 4; mt++)
        #pragma unroll
        for (int nt = 0; nt < 4; nt++)
            #pragma unroll
            for (int e = 0; e < 4; e++) acc[mt][nt][e] = 0.0f;

    int l_row = tid >> 1;
    int l_seg = tid & 1;

    #define LOAD_STAGE(s, kc) do {                                            \
        uint32_t d_ = sbase + (s) * STAGE2_B + l_row * 48 + l_seg * 16;       \
        const __nv_bfloat16* a_ = Ah + (size_t)(bm + l_row) * DM              \
                                  + ((kc) << 4) + l_seg * 8;                  \
        const __nv_bfloat16* b_ = Bh + (size_t)(bn + l_row) * DM              \
                                  + ((kc) << 4) + l_seg * 8;                  \
        cpasync16(d_, a_);                                                    \
        if (has_al) cpasync16(d_ + ARR2_B, Al + (a_ - Ah));                   \
        cpasync16(d_ + 2 * ARR2_B, b_);                                       \
        cpasync16(d_ + 3 * ARR2_B, Bl + (b_ - Bh));                           \
        CP_COMMIT();                                                          \
    } while (0)

    LOAD_STAGE(0, 0);
    LOAD_STAGE(1, 1);
    LOAD_STAGE(2, 2);

    const int NK = DM / 16;   // 64 chunks
    for (int kc = 0; kc < NK; kc++) {
        if (kc < NK - 3) CP_WAIT2();
        else             CP_WAIT0();
        __syncthreads();
        if (kc + 3 < NK) LOAD_STAGE((kc + 3) & 3, kc + 3);

        uint32_t sb = sbase + (kc & 3) * STAGE2_B;
        uint32_t ah[4][4], al[4][4];
        uint32_t a_addr = sb + (wm + (lane & 15)) * 48 + ((lane >> 4) << 4);
        #pragma unroll
        for (int mt = 0; mt < 4; mt++) {
            ldmat4(ah[mt], a_addr + mt * (16 * 48));
            if (has_al) ldmat4(al[mt], a_addr + mt * (16 * 48) + ARR2_B);
        }
        #pragma unroll
        for (int p = 0; p < 2; p++) {
            uint32_t bh4[4], bl4[4];
            uint32_t b_addr = sb + 2 * ARR2_B +
                (wn + (p << 4) + (lane & 7) + ((lane >> 4) << 3)) * 48 +
                (((lane >> 3) & 1) << 4);
            ldmat4(bh4, b_addr);
            ldmat4(bl4, b_addr + ARR2_B);
            #pragma unroll
            for (int mt = 0; mt < 4; mt++) {
                mma_bf16(acc[mt][2 * p],     ah[mt], bh4);
                mma_bf16(acc[mt][2 * p],     ah[mt], bl4);
                if (has_al) mma_bf16(acc[mt][2 * p], al[mt], bh4);
                mma_bf16(acc[mt][2 * p + 1], ah[mt], bh4 + 2);
                mma_bf16(acc[mt][2 * p + 1], ah[mt], bl4 + 2);
                if (has_al) mma_bf16(acc[mt][2 * p + 1], al[mt], bh4 + 2);
            }
        }
    }

    int rq = lane >> 2, cq = (lane & 3) << 1;
    if (C) {
        #pragma unroll
        for (int mt = 0; mt < 4; mt++) {
            int r0 = bm + wm + (mt << 4) + rq;
            #pragma unroll
            for (int nt = 0; nt < 4; nt++) {
                int c = bn + wn + (nt << 3) + cq;
                float2 v0 = make_float2(acc[mt][nt][0], acc[mt][nt][1]);
                float2 v1 = make_float2(acc[mt][nt][2], acc[mt][nt][3]);
                if (R) {
                    float2 r0v = *(const float2*)(R + (size_t)r0 * DM + c);
                    float2 r1v = *(const float2*)(R + (size_t)(r0 + 8) * DM + c);
                    v0.x += r0v.x; v0.y += r0v.y;
                    v1.x += r1v.x; v1.y += r1v.y;
                }
                *(float2*)(C + (size_t)r0 * DM + c) = v0;
                *(float2*)(C + (size_t)(r0 + 8) * DM + c) = v1;
            }
        }
    } else {
        #pragma unroll
        for (int mt = 0; mt < 4; mt++) {
            int r0 = bm + wm + (mt << 4) + rq;
            #pragma unroll
            for (int nt = 0; nt < 4; nt++) {
                int c = bn + wn + (nt << 3) + cq;
                store2_split(Ch, Cl, (size_t)r0 * DM + c,
                             acc[mt][nt][0], acc[mt][nt][1]);
                store2_split(Ch, Cl, (size_t)(r0 + 8) * DM + c,
                             acc[mt][nt][2], acc[mt][nt][3]);
            }
        }
    }
    #undef LOAD_STAGE
}

// Batched QKV projections (grid.z selects input/weights/output; all split-3)
__global__ void __launch_bounds__(256, 2) hmma_qkv(
    const __nv_bfloat16* A0h, const __nv_bfloat16* A0l,
    const __nv_bfloat16* A1h, const __nv_bfloat16* A1l,
    const __nv_bfloat16* A2h, const __nv_bfloat16* A2l,
    const __nv_bfloat16* WThB, const __nv_bfloat16* WTlB,
    __nv_bfloat16* C0h, __nv_bfloat16* C0l,
    __nv_bfloat16* C1h, __nv_bfloat16* C1l,
    __nv_bfloat16* C2h, __nv_bfloat16* C2l)
{
    extern __shared__ char dynsm[];
    int z = blockIdx.z;
    const __nv_bfloat16* Ah = (z == 0) ? A0h : (z == 1) ? A1h : A2h;
    const __nv_bfloat16* Al = (z == 0) ? A0l : (z == 1) ? A1l : A2l;
    __nv_bfloat16* Ch = (z == 0) ? C0h : (z == 1) ? C1h : C2h;
    __nv_bfloat16* Cl = (z == 0) ? C0l : (z == 1) ? C1l : C2l;
    gemm_body(Ah, Al, WThB + (size_t)z * DM * DM, WTlB + (size_t)z * DM * DM,
              nullptr, nullptr, Ch, Cl, dynsm);
}

// Single GEMM (used for Wo: Al=null -> 2-term, fp32 out + residual)
__global__ void __launch_bounds__(256, 2) hmma_single(
    const __nv_bfloat16* Ah, const __nv_bfloat16* Al,
    const __nv_bfloat16* Bh, const __nv_bfloat16* Bl,
    const float* R, float* C, __nv_bfloat16* Ch, __nv_bfloat16* Cl)
{
    extern __shared__ char dynsm[];
    gemm_body(Ah, Al, Bh, Bl, R, C, Ch, Cl, dynsm);
}

// ---------------------------------------------------------------------------
// V transpose: Vs hi/lo [8192][1024] -> Vt hi/lo [bh][64 d][2048 s]
// ---------------------------------------------------------------------------
__global__ void __launch_bounds__(256) vtrans_kernel(
    const __nv_bfloat16* __restrict__ Vh, const __nv_bfloat16* __restrict__ Vl,
    __nv_bfloat16* __restrict__ Th, __nv_bfloat16* __restrict__ Tl)
{
    __shared__ __nv_bfloat16 th[32][33], tl[32][33];
    int rt = blockIdx.x << 5;
    int ct = blockIdx.y << 5;
    int x = threadIdx.x & 31, y = threadIdx.x >> 5;
    #pragma unroll
    for (int r = 0; r < 32; r += 8) {
        th[y + r][x] = Vh[(size_t)(rt + y + r) * DM + ct + x];
        tl[y + r][x] = Vl[(size_t)(rt + y + r) * DM + ct + x];
    }
    __syncthreads();
    int b = rt >> 11;
    int s0 = rt & 2047;
    #pragma unroll
    for (int r = 0; r < 32; r += 8) {
        int col = ct + y + r;
        int h = col >> 6, d = col & 63;
        size_t o = ((size_t)(b * H_ + h) * DK + d) * S_ + s0 + x;
        Th[o] = th[x][y + r];
        Tl[o] = tl[x][y + r];
    }
}

// ---------------------------------------------------------------------------
// scores2: per block 128 q-rows x full 2048 k (split-3, unchanged math).
// ---------------------------------------------------------------------------
__global__ void __launch_bounds__(256, 2) scores2_kernel(
    const __nv_bfloat16* __restrict__ Qsh, const __nv_bfloat16* __restrict__ Qsl,
    const __nv_bfloat16* __restrict__ Ksh, const __nv_bfloat16* __restrict__ Ksl,
    const int* __restrict__ mask, float* __restrict__ attn,
    float* __restrict__ tm, float* __restrict__ rowM, float* __restrict__ rowS)
{
    extern __shared__ char dsm[];
    uint32_t sb = smem_u32(dsm);
    const uint32_t sQh = sb;
    const uint32_t sQl = sb + 18432;
    const uint32_t sKh = sb + 36864;
    const uint32_t sKl = sb + 73728;
    __shared__ int msk[2][128];

    int tid = threadIdx.x, lane = tid & 31, wid = tid >> 5;
    int bh = blockIdx.y, b = bh >> 4, h = bh & 15;
    int q0 = blockIdx.x << 7;
    int ql = lane >> 2, cq = (lane & 3) << 1;

    #pragma unroll
    for (int i = 0; i < 4; i++) {
        int sidx = tid + (i << 8);
        int row = sidx >> 3, off = (sidx & 7) << 3;
        uint32_t d = (uint32_t)((row * 72 + off) << 1);
        size_t go = (size_t)(b * S_ + q0 + row) * DM + h * DK + off;
        cpasync16(sQh + d, Qsh + go);
        cpasync16(sQl + d, Qsl + go);
    }

    #define LOADK(st, kt) do {                                                \
        int kb_ = (kt) << 7;                                                  \
        if (tid < 128) msk[st][tid] = mask[b * S_ + kb_ + tid];               \
        _Pragma("unroll")                                                     \
        for (int i = 0; i < 4; i++) {                                         \
            int sidx = tid + (i << 8);                                        \
            int row = sidx >> 3, off = (sidx & 7) << 3;                       \
            uint32_t d = (uint32_t)(((st) * 18432) + ((row * 72 + off) << 1));\
            size_t go = (size_t)(b * S_ + kb_ + row) * DM + h * DK + off;     \
            cpasync16(sKh + d, Ksh + go);                                     \
            cpasync16(sKl + d, Ksl + go);                                     \
        }                                                                     \
    } while (0)

    LOADK(0, 0);
    CP_COMMIT();
    LOADK(1, 1);
    CP_COMMIT();
    CP_WAIT1();
    __syncthreads();

    uint32_t qh4[4][4], ql4[4][4];
    #pragma unroll
    for (int ks = 0; ks < 4; ks++) {
        uint32_t aaddr = sQh +
            ((((wid << 4) + (lane & 15)) * 72 + (ks << 4) +
              ((lane >> 4) << 3)) << 1);
        ldmat4(qh4[ks], aaddr);
        ldmat4(ql4[ks], aaddr + 18432);
    }

    float m0 = -3.0e38f, m1 = -3.0e38f, sg0 = 0.0f, sg1 = 0.0f;
    int wrow = (wid << 4) + ql;
    size_t R0 = (size_t)bh * S_ + q0 + wrow;

    for (int kt = 0; kt < 16; kt++) {
        int st = kt & 1;
        uint32_t kbase = sKh + st * 18432;
        int kb = kt << 7;

        #pragma unroll
        for (int hf = 0; hf < 2; hf++) {
            float acc[8][4];
            #pragma unroll
            for (int nt = 0; nt < 8; nt++)
                #pragma unroll
                for (int e = 0; e < 4; e++) acc[nt][e] = 0.0f;

            #pragma unroll
            for (int ks = 0; ks < 4; ks++) {
                #pragma unroll
                for (int p = 0; p < 4; p++) {
                    int pp = (hf << 2) + p;
                    uint32_t bh4[4], bl4[4];
                    uint32_t baddr = kbase +
                        ((((pp << 4) + (lane & 7) + ((lane >> 4) << 3)) * 72 +
                          (ks << 4) + (((lane >> 3) & 1) << 3)) << 1);
                    ldmat4(bh4, baddr);
                    ldmat4(bl4, baddr + 36864);
                    mma_bf16(acc[2 * p],     qh4[ks], bh4);
                    mma_bf16(acc[2 * p],     qh4[ks], bl4);
                    mma_bf16(acc[2 * p],     ql4[ks], bh4);
                    mma_bf16(acc[2 * p + 1], qh4[ks], bh4 + 2);
                    mma_bf16(acc[2 * p + 1], qh4[ks], bl4 + 2);
                    mma_bf16(acc[2 * p + 1], ql4[ks], bh4 + 2);
                }
            }

            float mx0 = -3.0e38f, mx1 = -3.0e38f;
            #pragma unroll
            for (int nt = 0; nt < 8; nt++) {
                int c0 = (hf << 6) + (nt << 3) + cq;
                bool k0m = msk[st][c0] != 0;
                bool k1m = msk[st][c0 + 1] != 0;
                acc[nt][0] = k0m ? acc[nt][0] : NEG_INF_F;
                acc[nt][1] = k1m ? acc[nt][1] : NEG_INF_F;
                acc[nt][2] = k0m ? acc[nt][2] : NEG_INF_F;
                acc[nt][3] = k1m ? acc[nt][3] : NEG_INF_F;
                mx0 = fmaxf(mx0, fmaxf(acc[nt][0], acc[nt][1]));
                mx1 = fmaxf(mx1, fmaxf(acc[nt][2], acc[nt][3]));
            }
            mx0 = fmaxf(mx0, __shfl_xor_sync(0xffffffffu, mx0, 1));
            mx0 = fmaxf(mx0, __shfl_xor_sync(0xffffffffu, mx0, 2));
            mx1 = fmaxf(mx1, __shfl_xor_sync(0xffffffffu, mx1, 1));
            mx1 = fmaxf(mx1, __shfl_xor_sync(0xffffffffu, mx1, 2));
            float mp0 = m0; m0 = fmaxf(m0, mx0); sg0 *= __expf(mp0 - m0);
            float mp1 = m1; m1 = fmaxf(m1, mx1); sg1 *= __expf(mp1 - m1);

            float* o0 = attn + R0 * S_ + kb;
            float* o1 = attn + (R0 + 8) * S_ + kb;
            #pragma unroll
            for (int nt = 0; nt < 8; nt++) {
                int c0 = (hf << 6) + (nt << 3) + cq;
                float e0 = __expf(acc[nt][0] - m0), e1 = __expf(acc[nt][1] - m0);
                float e2 = __expf(acc[nt][2] - m1), e3 = __expf(acc[nt][3] - m1);
                sg0 += e0 + e1;
                sg1 += e2 + e3;
                *(float2*)(o0 + c0) = make_float2(e0, e1);
                *(float2*)(o1 + c0) = make_float2(e2, e3);
            }
            if ((lane & 3) == 0) {
                int t2 = (kt << 1) + hf;
                tm[R0 * NTILE + t2]       = m0;
                tm[(R0 + 8) * NTILE + t2] = m1;
            }
        }

        __syncthreads();
        if (kt + 2 < 16) {
            LOADK(st, kt + 2);
            CP_COMMIT();
            CP_WAIT1();
        } else {
            CP_WAIT0();
        }
        __syncthreads();
    }

    sg0 += __shfl_xor_sync(0xffffffffu, sg0, 1);
    sg0 += __shfl_xor_sync(0xffffffffu, sg0, 2);
    sg1 += __shfl_xor_sync(0xffffffffu, sg1, 1);
    sg1 += __shfl_xor_sync(0xffffffffu, sg1, 2);
    if ((lane & 3) == 0) {
        rowM[R0] = m0;      rowS[R0] = sg0;
        rowM[R0 + 8] = m1;  rowS[R0 + 8] = sg1;
    }
    #undef LOADK
}

// ---------------------------------------------------------------------------
// finalize: scale[row][tile] = exp(m_t - M) / sigma
// ---------------------------------------------------------------------------
__global__ void __launch_bounds__(256) fin_kernel(
    const float* __restrict__ tm, const float* __restrict__ rM,
    const float* __restrict__ rS, float* __restrict__ tsc)
{
    int i = blockIdx.x * 256 + threadIdx.x;
    int R = i >> 5;           // NTILE = 32
    tsc[i] = __expf(tm[i] - rM[R]) / rS[R];
}

// ---------------------------------------------------------------------------
// normPV: p = E * scale (in-place, fp32 exact — attn output precision kept),
// ctx = Ph @ (Vh+Vl) [2-term, Pl dropped], ctx stored bf16-hi only.
// Dyn smem: Ph (34816) + Vh|Vl (17408 ea) = 69632 B.
// ---------------------------------------------------------------------------
__global__ void __launch_bounds__(256, 2) normpv_kernel(
    float* __restrict__ attn, const float* __restrict__ tsc,
    const __nv_bfloat16* __restrict__ Vth, const __nv_bfloat16* __restrict__ Vtl,
    __nv_bfloat16* __restrict__ Ch)
{
    extern __shared__ char dsm[];
    uint32_t sb = smem_u32(dsm);
    const uint32_t sPh = sb;
    const uint32_t sVh = sb + 34816;
    const uint32_t sVl = sb + 52224;

    int tid = threadIdx.x, lane = tid & 31, wid = tid >> 5;
    int bh = blockIdx.y, b = bh >> 4, h = bh & 15;
    int q0 = blockIdx.x << 7;
    int wm = (wid & 3) << 5, wn = (wid >> 2) << 5;
    int rq = lane >> 2, cq = (lane & 3) << 1;

    float acc[2][4][4];
    #pragma unroll
    for (int mt = 0; mt < 2; mt++)
        #pragma unroll
        for (int nt = 0; nt < 4; nt++)
            #pragma unroll
            for (int e = 0; e < 4; e++) acc[mt][nt][e] = 0.0f;

    size_t Rbase = (size_t)bh * S_ + q0 + (wid << 4);

    for (int kt = 0; kt < 16; kt++) {
        int kb = kt << 7;
        #pragma unroll
        for (int i = 0; i < 4; i++) {
            int sidx = tid + (i << 8);
            int d = sidx >> 4, off = (sidx & 15) << 3;
            uint32_t dst = (uint32_t)((d * 136 + off) << 1);
            size_t go = ((size_t)bh * DK + d) * S_ + kb + off;
            cpasync16(sVh + dst, Vth + go);
            cpasync16(sVl + dst, Vtl + go);
        }
        CP_COMMIT();

        #pragma unroll 4
        for (int r = 0; r < 16; r++) {
            int row = (wid << 4) + r;
            size_t Rr = Rbase + r;
            float sc = tsc[Rr * NTILE + (kt << 1) + (lane >> 4)];
            float* erow = attn + Rr * S_ + kb + (lane << 2);
            float4 vv = *(const float4*)erow;
            float p0 = vv.x * sc, p1 = vv.y * sc, p2 = vv.z * sc, p3 = vv.w * sc;
            *(float4*)erow = make_float4(p0, p1, p2, p3);
            U4 hh;
            hh.h[0] = __float2bfloat16(p0);
            hh.h[1] = __float2bfloat16(p1);
            hh.h[2] = __float2bfloat16(p2);
            hh.h[3] = __float2bfloat16(p3);
            uint32_t doff = (uint32_t)((row * 136 + (lane << 2)) << 1);
            sts64(sPh + doff, hh.u);
        }
        CP_WAIT0();
        __syncthreads();

        #pragma unroll
        for (int ks = 0; ks < 8; ks++) {
            uint32_t ah4[2][4];
            #pragma unroll
            for (int mt = 0; mt < 2; mt++) {
                uint32_t aaddr = sPh +
                    (((wm + (mt << 4) + (lane & 15)) * 136 +
                      (ks << 4) + ((lane >> 4) << 3)) << 1);
                ldmat4(ah4[mt], aaddr);
            }
            #pragma unroll
            for (int p = 0; p < 2; p++) {
                uint32_t bh4[4], bl4[4];
                uint32_t baddr = sVh +
                    (((wn + (p << 4) + (lane & 7) + ((lane >> 4) << 3)) * 136 +
                      (ks << 4) + (((lane >> 3) & 1) << 3)) << 1);
                ldmat4(bh4, baddr);
                ldmat4(bl4, baddr + 17408);
                #pragma unroll
                for (int mt = 0; mt < 2; mt++) {
                    mma_bf16(acc[mt][2 * p],     ah4[mt], bh4);
                    mma_bf16(acc[mt][2 * p],     ah4[mt], bl4);
                    mma_bf16(acc[mt][2 * p + 1], ah4[mt], bh4 + 2);
                    mma_bf16(acc[mt][2 * p + 1], ah4[mt], bl4 + 2);
                }
            }
        }
        __syncthreads();
    }

    // ctx epilogue -> bf16 hi only
    #pragma unroll
    for (int mt = 0; mt < 2; mt++) {
        int row = b * S_ + q0 + wm + (mt << 4) + rq;
        #pragma unroll
        for (int nt = 0; nt < 4; nt++) {
            int col = h * DK + wn + (nt << 3) + cq;
            U2 h0, h1;
            h0.h[0] = __float2bfloat16(acc[mt][nt][0]);
            h0.h[1] = __float2bfloat16(acc[mt][nt][1]);
            h1.h[0] = __float2bfloat16(acc[mt][nt][2]);
            h1.h[1] = __float2bfloat16(acc[mt][nt][3]);
            *(uint32_t*)(Ch + (size_t)row * DM + col)       = h0.u;
            *(uint32_t*)(Ch + (size_t)(row + 8) * DM + col) = h1.u;
        }
    }
}

// ---------------------------------------------------------------------------
extern "C" void kernel_launch(void* const* d_in, const int* in_sizes, int n_in,
                              void* d_out, int out_size)
{
    const float* q    = (const float*)d_in[0];
    const float* k    = (const float*)d_in[1];
    const float* v    = (const float*)d_in[2];
    const int*   mask = (const int*)  d_in[3];
    const float* Wq   = (const float*)d_in[4];
    const float* Wk   = (const float*)d_in[5];
    const float* Wv   = (const float*)d_in[6];
    const float* Wo   = (const float*)d_in[7];
    const float* lg   = (const float*)d_in[8];
    const float* lb   = (const float*)d_in[9];

    float* out  = (float*)d_out;
    float* attn = out + ATTN_OFF;

    __nv_bfloat16 *WTh, *WTl, *Ah, *Al, *Qsh, *Qsl, *Ksh, *Ksl, *Vsh, *Vsl,
                  *Vth, *Vtl, *Ch, *Cl;
    float *tm, *tsc, *rM, *rS;
    cudaGetSymbolAddress((void**)&WTh, g_WTh);
    cudaGetSymbolAddress((void**)&WTl, g_WTl);
    cudaGetSymbolAddress((void**)&Ah,  g_Ah);
    cudaGetSymbolAddress((void**)&Al,  g_Al);
    cudaGetSymbolAddress((void**)&Qsh, g_Qsh);
    cudaGetSymbolAddress((void**)&Qsl, g_Qsl);
    cudaGetSymbolAddress((void**)&Ksh, g_Ksh);
    cudaGetSymbolAddress((void**)&Ksl, g_Ksl);
    cudaGetSymbolAddress((void**)&Vsh, g_Vsh);
    cudaGetSymbolAddress((void**)&Vsl, g_Vsl);
    cudaGetSymbolAddress((void**)&Vth, g_Vth);
    cudaGetSymbolAddress((void**)&Vtl, g_Vtl);
    cudaGetSymbolAddress((void**)&Ch,  g_Ch);
    cudaGetSymbolAddress((void**)&Cl,  g_Cl);
    cudaGetSymbolAddress((void**)&tm,  g_tm);
    cudaGetSymbolAddress((void**)&tsc, g_tsc);
    cudaGetSymbolAddress((void**)&rM,  g_rowM);
    cudaGetSymbolAddress((void**)&rS,  g_rowS);

    cudaFuncSetAttribute(hmma_qkv,
                         cudaFuncAttributeMaxDynamicSharedMemorySize, GEMM_SMEM);
    cudaFuncSetAttribute(hmma_single,
                         cudaFuncAttributeMaxDynamicSharedMemorySize, GEMM_SMEM);
    cudaFuncSetAttribute(scores2_kernel,
                         cudaFuncAttributeMaxDynamicSharedMemorySize, 110592);
    cudaFuncSetAttribute(normpv_kernel,
                         cudaFuncAttributeMaxDynamicSharedMemorySize, 69632);

    // 1. All weight transposes in one launch (Wq folded with 0.125)
    wtrans4_kernel<<<dim3(32, 32, 4), 256>>>(Wq, Wk, Wv, Wo, WTh, WTl);

    // 2. LayerNorm(q) -> split (Q input)
    ln_split_kernel<<<BS_, 256>>>(q, lg, lb, (uint2*)Ah, (uint2*)Al);

    // 3. Split k -> (Ch,Cl), v -> (Vth,Vtl)   [buffers reused later]
    asplit2_kernel<<<dim3(BS_ * DM / 4 / 256, 2), 256>>>(
        (const float4*)k, (uint2*)Ch, (uint2*)Cl,
        (const float4*)v, (uint2*)Vth, (uint2*)Vtl);

    // 4. Q/K/V projections in ONE batched launch (split-3)
    hmma_qkv<<<dim3(DM / 128, BS_ / 128, 3), 256, GEMM_SMEM>>>(
        Ah, Al, Ch, Cl, Vth, Vtl, WTh, WTl,
        Qsh, Qsl, Ksh, Ksl, Vsh, Vsl);

    // 5. V transpose to [bh][d][s] (overwrites V-split input, already consumed)
    vtrans_kernel<<<dim3(BS_ / 32, DM / 32), 256>>>(Vsh, Vsl, Vth, Vtl);

    // 6. Scores: E = exp(s - m_t) with per-64-col-tile m_t
    scores2_kernel<<<dim3(S_ / 128, B_ * H_), 256, 110592>>>(
        Qsh, Qsl, Ksh, Ksl, mask, attn, tm, rM, rS);

    // 7. Per-(row, tile) scales
    fin_kernel<<<(NROW * NTILE) / 256, 256>>>(tm, rM, rS, tsc);

    // 8. Normalize probs in place (fp32 exact) + PV 2-term; ctx bf16-hi
    normpv_kernel<<<dim3(S_ / 128, B_ * H_), 256, 69632>>>(
        attn, tsc, Vth, Vtl, Ch);

    // 9. Output projection (2-term: ctx-hi only) + residual
    hmma_single<<<dim3(DM / 128, BS_ / 128), 256, GEMM_SMEM>>>(
        Ch, nullptr, WTh + 3 * (size_t)DM * DM, WTl + 3 * (size_t)DM * DM,
        q, out, nullptr, nullptr);
}